// round 4
// baseline (speedup 1.0000x reference)
#include <cuda_runtime.h>
#include <math.h>

#define N_PTS 2048
#define C_IN  512
#define KNN   40
#define C5    512              // conv5 out channels == attention S
#define C6    515              // conv6 out channels == attention feature dim
#define INDIM C6               // attention input feature dim (515)
#define NKCOL (KNN*C5)         // 20480
#define HD    512              // HDIM
#define NH    8
#define AD    64
#define SOFT_SCALE 0.04419417382415922f  // 512^-0.5

// ---------------- scratch (device globals, no runtime alloc) ----------------
__device__ float g_dist[(size_t)N_PTS*N_PTS];        // 16 MB
__device__ int   g_idx[N_PTS*KNN];
__device__ float g_xx[N_PTS];
__device__ float g_At[(size_t)N_PTS*C5];             // [j][c]  (bn5-folded gather term)
__device__ float g_Ct[(size_t)N_PTS*C5];             // [n][c]  (bn5-folded center term)
__device__ float g_L [(size_t)N_PTS*NKCOL];          // 168 MB  L[n][k*512+c]
__device__ float g_o2[(size_t)C6*NKCOL];             // 42 MB   out2[o][k*512+c]
__device__ float g_xf[C5*C6];
__device__ float g_yf[C5*C6];
__device__ float g_q [C5*HD];
__device__ float g_k [C5*HD];
__device__ float g_v [C5*HD];
__device__ float g_sc[(size_t)NH*C5*C5];             // 8 MB
__device__ float g_mg[C5*HD];

__device__ __forceinline__ float lrelu(float v){ return v > 0.f ? v : 0.2f*v; }

// ---------------- xx[n] = sum_c x[c,n]^2 ----------------
__global__ void k_xx(const float* __restrict__ x){
    int n = blockIdx.x*blockDim.x + threadIdx.x;
    if(n < N_PTS){
        float s = 0.f;
        for(int c = 0; c < C_IN; c++){ float v = x[(size_t)c*N_PTS + n]; s += v*v; }
        g_xx[n] = s;
    }
}

// ---------------- neg sq dist: D[n][m] = 2*inner - xx[n] - xx[m] ----------------
__global__ __launch_bounds__(256) void k_dist(const float* __restrict__ x){
    __shared__ __align__(16) float sN[16][64];
    __shared__ __align__(16) float sM[16][64];
    int tx = threadIdx.x, ty = threadIdx.y, t = ty*16 + tx;
    int n0 = blockIdx.y*64, m0 = blockIdx.x*64;
    float acc[4][4] = {};
    for(int c0 = 0; c0 < C_IN; c0 += 16){
        #pragma unroll
        for(int i = 0; i < 4; i++){
            int e = t + i*256; int kt = e >> 6; int col = e & 63;
            sN[kt][col] = x[(size_t)(c0+kt)*N_PTS + n0 + col];
            sM[kt][col] = x[(size_t)(c0+kt)*N_PTS + m0 + col];
        }
        __syncthreads();
        #pragma unroll
        for(int kk = 0; kk < 16; kk++){
            float4 a4 = *(const float4*)&sN[kk][ty*4];
            float4 b4 = *(const float4*)&sM[kk][tx*4];
            float av[4] = {a4.x,a4.y,a4.z,a4.w};
            float bv[4] = {b4.x,b4.y,b4.z,b4.w};
            #pragma unroll
            for(int i = 0; i < 4; i++)
                #pragma unroll
                for(int j = 0; j < 4; j++) acc[i][j] += av[i]*bv[j];
        }
        __syncthreads();
    }
    #pragma unroll
    for(int i = 0; i < 4; i++){
        int n = n0 + ty*4 + i; float xn = g_xx[n];
        #pragma unroll
        for(int j = 0; j < 4; j++){
            int m = m0 + tx*4 + j;
            g_dist[(size_t)n*N_PTS + m] = 2.f*acc[i][j] - xn - g_xx[m];
        }
    }
}

// ---------------- top-40 per row (desc value, lower index on ties) ----------------
__global__ __launch_bounds__(256) void k_topk(){
    int n = blockIdx.x;
    __shared__ float sv[N_PTS];
    __shared__ float rv[256];
    __shared__ int   ri[256];
    int t = threadIdx.x;
    for(int i = t; i < N_PTS; i += 256) sv[i] = g_dist[(size_t)n*N_PTS + i];
    __syncthreads();
    for(int kk = 0; kk < KNN; kk++){
        float bv = -INFINITY; int bi = N_PTS;
        for(int i = t; i < N_PTS; i += 256){
            float v = sv[i];
            if(v > bv || (v == bv && i < bi)){ bv = v; bi = i; }
        }
        rv[t] = bv; ri[t] = bi; __syncthreads();
        for(int s = 128; s > 0; s >>= 1){
            if(t < s){
                float v = rv[t+s]; int i2 = ri[t+s];
                if(v > rv[t] || (v == rv[t] && i2 < ri[t])){ rv[t] = v; ri[t] = i2; }
            }
            __syncthreads();
        }
        if(t == 0){ g_idx[n*KNN + kk] = ri[0]; sv[ri[0]] = -INFINITY; }
        __syncthreads();
    }
}

// ---------------- folded conv5: At[j][o]=s5*W5a@x ; Ct[n][o]=s5*(W5b-W5a)@x + t5 ----------------
__global__ __launch_bounds__(256) void k_ac(const float* __restrict__ x, const float* __restrict__ w5,
                        const float* __restrict__ g5, const float* __restrict__ b5,
                        const float* __restrict__ m5, const float* __restrict__ v5){
    __shared__ __align__(16) float sX[16][64];
    __shared__ float sWa[64][17];
    __shared__ float sWd[64][17];
    int tx = threadIdx.x, ty = threadIdx.y, t = ty*16 + tx;
    int j0 = blockIdx.y*64, o0 = blockIdx.x*64;
    float accA[4][4] = {}, accC[4][4] = {};
    for(int c0 = 0; c0 < C_IN; c0 += 16){
        #pragma unroll
        for(int i = 0; i < 4; i++){
            int e = t + i*256; int kt = e >> 6; int col = e & 63;
            sX[kt][col] = x[(size_t)(c0+kt)*N_PTS + j0 + col];
        }
        #pragma unroll
        for(int i = 0; i < 4; i++){
            int e = t + i*256; int kt = e & 15; int oi = e >> 4;
            float wa = w5[(size_t)(o0+oi)*1024 + c0 + kt];
            float wb = w5[(size_t)(o0+oi)*1024 + 512 + c0 + kt];
            sWa[oi][kt] = wa; sWd[oi][kt] = wb - wa;
        }
        __syncthreads();
        #pragma unroll
        for(int kk = 0; kk < 16; kk++){
            float4 x4 = *(const float4*)&sX[kk][ty*4];
            float xv[4] = {x4.x,x4.y,x4.z,x4.w};
            float wa[4], wd[4];
            #pragma unroll
            for(int j = 0; j < 4; j++){ wa[j] = sWa[tx*4+j][kk]; wd[j] = sWd[tx*4+j][kk]; }
            #pragma unroll
            for(int i = 0; i < 4; i++)
                #pragma unroll
                for(int j = 0; j < 4; j++){ accA[i][j] += xv[i]*wa[j]; accC[i][j] += xv[i]*wd[j]; }
        }
        __syncthreads();
    }
    #pragma unroll
    for(int j = 0; j < 4; j++){
        int o = o0 + tx*4 + j;
        float s = g5[o]*rsqrtf(v5[o] + 1e-5f);
        float tt = b5[o] - m5[o]*s;
        #pragma unroll
        for(int i = 0; i < 4; i++){
            int jj = j0 + ty*4 + i;
            g_At[(size_t)jj*C5 + o] = s*accA[i][j];
            g_Ct[(size_t)jj*C5 + o] = s*accC[i][j] + tt;
        }
    }
}

// ---------------- L[n][k*512+c] = lrelu(At[idx[n,k]][c] + Ct[n][c]) ----------------
__global__ void k_buildL(){
    int k = blockIdx.x, n = blockIdx.y;
    int j = g_idx[n*KNN + k];
    const float4* a = (const float4*)(g_At + (size_t)j*C5);
    const float4* c = (const float4*)(g_Ct + (size_t)n*C5);
    float4* o = (float4*)(g_L + (size_t)n*NKCOL + (size_t)k*C5);
    int t = threadIdx.x; // 128 threads * 4 floats = 512
    float4 av = a[t], cv = c[t];
    float4 r;
    r.x = lrelu(av.x + cv.x); r.y = lrelu(av.y + cv.y);
    r.z = lrelu(av.z + cv.z); r.w = lrelu(av.w + cv.w);
    o[t] = r;
}

// ---------------- generic gemm_nn: C[m][n] = sum_k A[m,k]*B[k,n] ----------------
__global__ __launch_bounds__(256) void gemm_nn(const float* __restrict__ A, const float* __restrict__ B,
                       float* __restrict__ C, int M, int N, int K,
                       int lda, int ldb, int ldc,
                       long long sA, long long sB, long long sC){
    A += (size_t)blockIdx.z * sA; B += (size_t)blockIdx.z * sB; C += (size_t)blockIdx.z * sC;
    __shared__ float sAp[64][17];
    __shared__ __align__(16) float sBt[16][64];
    int tx = threadIdx.x, ty = threadIdx.y, t = ty*16 + tx;
    int m0 = blockIdx.y*64, n0 = blockIdx.x*64;
    float acc[4][4] = {};
    for(int k0 = 0; k0 < K; k0 += 16){
        #pragma unroll
        for(int i = 0; i < 4; i++){
            int e = t + i*256; int kt = e & 15; int mi = e >> 4;
            int m = m0 + mi, k = k0 + kt;
            sAp[mi][kt] = (m < M && k < K) ? A[(size_t)m*lda + k] : 0.f;
        }
        #pragma unroll
        for(int i = 0; i < 4; i++){
            int e = t + i*256; int ni = e & 63; int kt = e >> 6;
            int k = k0 + kt, n = n0 + ni;
            sBt[kt][ni] = (k < K && n < N) ? B[(size_t)k*ldb + n] : 0.f;
        }
        __syncthreads();
        #pragma unroll
        for(int kk = 0; kk < 16; kk++){
            float av[4];
            #pragma unroll
            for(int i = 0; i < 4; i++) av[i] = sAp[ty*4+i][kk];
            float4 b4 = *(const float4*)&sBt[kk][tx*4];
            float bv[4] = {b4.x,b4.y,b4.z,b4.w};
            #pragma unroll
            for(int i = 0; i < 4; i++)
                #pragma unroll
                for(int j = 0; j < 4; j++) acc[i][j] += av[i]*bv[j];
        }
        __syncthreads();
    }
    #pragma unroll
    for(int i = 0; i < 4; i++){
        int m = m0 + ty*4 + i; if(m >= M) continue;
        #pragma unroll
        for(int j = 0; j < 4; j++){
            int n = n0 + tx*4 + j; if(n >= N) continue;
            C[(size_t)m*ldc + n] = acc[i][j];
        }
    }
}

// ---------------- generic gemm_nt: C[m][n] = sum_k A[m,k]*B[n,k] (+bias[n]) ----------------
__global__ __launch_bounds__(256) void gemm_nt(const float* __restrict__ A, const float* __restrict__ B,
                       float* __restrict__ C, int M, int N, int K,
                       int lda, int ldb, int ldc,
                       long long sA, long long sB, long long sC,
                       const float* __restrict__ bias){
    A += (size_t)blockIdx.z * sA; B += (size_t)blockIdx.z * sB; C += (size_t)blockIdx.z * sC;
    __shared__ float sAp[64][17];
    __shared__ float sBp[64][17];
    int tx = threadIdx.x, ty = threadIdx.y, t = ty*16 + tx;
    int m0 = blockIdx.y*64, n0 = blockIdx.x*64;
    float acc[4][4] = {};
    for(int k0 = 0; k0 < K; k0 += 16){
        #pragma unroll
        for(int i = 0; i < 4; i++){
            int e = t + i*256; int kt = e & 15; int mi = e >> 4;
            int m = m0 + mi, k = k0 + kt;
            sAp[mi][kt] = (m < M && k < K) ? A[(size_t)m*lda + k] : 0.f;
        }
        #pragma unroll
        for(int i = 0; i < 4; i++){
            int e = t + i*256; int kt = e & 15; int ni = e >> 4;
            int n = n0 + ni, k = k0 + kt;
            sBp[ni][kt] = (n < N && k < K) ? B[(size_t)n*ldb + k] : 0.f;
        }
        __syncthreads();
        #pragma unroll
        for(int kk = 0; kk < 16; kk++){
            float av[4], bv[4];
            #pragma unroll
            for(int i = 0; i < 4; i++) av[i] = sAp[ty*4+i][kk];
            #pragma unroll
            for(int j = 0; j < 4; j++) bv[j] = sBp[tx*4+j][kk];
            #pragma unroll
            for(int i = 0; i < 4; i++)
                #pragma unroll
                for(int j = 0; j < 4; j++) acc[i][j] += av[i]*bv[j];
        }
        __syncthreads();
    }
    #pragma unroll
    for(int i = 0; i < 4; i++){
        int m = m0 + ty*4 + i; if(m >= M) continue;
        #pragma unroll
        for(int j = 0; j < 4; j++){
            int n = n0 + tx*4 + j; if(n >= N) continue;
            float bb = bias ? bias[n] : 0.f;
            C[(size_t)m*ldc + n] = acc[i][j] + bb;
        }
    }
}

// ---------------- bn6 + lrelu + max over k:  f[c][o] ----------------
__global__ void k_maxpool(const float* __restrict__ g6, const float* __restrict__ b6,
                          const float* __restrict__ m6, const float* __restrict__ v6,
                          float* __restrict__ f){
    int o = blockIdx.y;
    int c = blockIdx.x*256 + threadIdx.x;
    float s = g6[o]*rsqrtf(v6[o] + 1e-5f);
    float t = b6[o] - m6[o]*s;
    const float* row = g_o2 + (size_t)o*NKCOL + c;
    float mx = -INFINITY;
    #pragma unroll 8
    for(int k = 0; k < KNN; k++){
        float h = s*row[(size_t)k*C5] + t;
        h = lrelu(h);
        mx = fmaxf(mx, h);
    }
    f[(size_t)c*C6 + o] = mx;
}

// ---------------- row softmax over scores (scale applied here) ----------------
__global__ __launch_bounds__(256) void k_softmax(){
    int r = blockIdx.x;
    float* p = g_sc + (size_t)r*C5;
    __shared__ float red[256];
    int t = threadIdx.x;
    float v0 = p[t]*SOFT_SCALE, v1 = p[t+256]*SOFT_SCALE;
    red[t] = fmaxf(v0, v1); __syncthreads();
    for(int s = 128; s > 0; s >>= 1){ if(t < s) red[t] = fmaxf(red[t], red[t+s]); __syncthreads(); }
    float mm = red[0]; __syncthreads();
    float e0 = __expf(v0 - mm), e1 = __expf(v1 - mm);
    red[t] = e0 + e1; __syncthreads();
    for(int s = 128; s > 0; s >>= 1){ if(t < s) red[t] += red[t+s]; __syncthreads(); }
    float inv = 1.f/red[0];
    p[t] = e0*inv; p[t+256] = e1*inv;
}

// =============================== host launcher ===============================
extern "C" void kernel_launch(void* const* d_in, const int* in_sizes, int n_in,
                              void* d_out, int out_size){
    const float* x    = (const float*)d_in[0];
    const float* y    = (const float*)d_in[1];
    const float* w5   = (const float*)d_in[2];
    const float* g5   = (const float*)d_in[3];
    const float* b5   = (const float*)d_in[4];
    const float* m5   = (const float*)d_in[5];
    const float* v5   = (const float*)d_in[6];
    const float* w6   = (const float*)d_in[7];
    const float* g6   = (const float*)d_in[8];
    const float* b6   = (const float*)d_in[9];
    const float* m6   = (const float*)d_in[10];
    const float* v6   = (const float*)d_in[11];
    const float* Wq   = (const float*)d_in[12];
    const float* Wk   = (const float*)d_in[13];
    const float* Wv   = (const float*)d_in[14];
    const float* Wout = (const float*)d_in[15];
    const float* bout = (const float*)d_in[16];
    float* out = (float*)d_out;

    float *pL, *pO2, *pxf, *pyf, *pq, *pk, *pv, *psc, *pm;
    cudaGetSymbolAddress((void**)&pL,  g_L);
    cudaGetSymbolAddress((void**)&pO2, g_o2);
    cudaGetSymbolAddress((void**)&pxf, g_xf);
    cudaGetSymbolAddress((void**)&pyf, g_yf);
    cudaGetSymbolAddress((void**)&pq,  g_q);
    cudaGetSymbolAddress((void**)&pk,  g_k);
    cudaGetSymbolAddress((void**)&pv,  g_v);
    cudaGetSymbolAddress((void**)&psc, g_sc);
    cudaGetSymbolAddress((void**)&pm,  g_mg);

    dim3 t2(16, 16);

    for(int br = 0; br < 2; br++){
        const float* p = br ? y : x;
        float* f = br ? pyf : pxf;

        k_xx<<<8, 256>>>(p);
        k_dist<<<dim3(32, 32), t2>>>(p);
        k_topk<<<N_PTS, 256>>>();
        k_ac<<<dim3(8, 32), t2>>>(p, w5, g5, b5, m5, v5);
        k_buildL<<<dim3(KNN, N_PTS), 128>>>();
        // out2[o][k*512+c] = sum_n w6[o,n] * L[n][k*512+c]
        gemm_nn<<<dim3(NKCOL/64, (C6+63)/64, 1), t2>>>(w6, pL, pO2,
                 C6, NKCOL, N_PTS, N_PTS, NKCOL, NKCOL, 0, 0, 0);
        k_maxpool<<<dim3(2, C6), 256>>>(g6, b6, m6, v6, f);
    }

    // q/k/v:  [512 x 512] = f[512 x 515] @ W^T[515 x 512]
    gemm_nt<<<dim3(8, 8, 1), t2>>>(pxf, Wq, pq, C5, HD, INDIM, INDIM, INDIM, HD, 0, 0, 0, nullptr);
    gemm_nt<<<dim3(8, 8, 1), t2>>>(pyf, Wk, pk, C5, HD, INDIM, INDIM, INDIM, HD, 0, 0, 0, nullptr);
    gemm_nt<<<dim3(8, 8, 1), t2>>>(pyf, Wv, pv, C5, HD, INDIM, INDIM, INDIM, HD, 0, 0, 0, nullptr);

    // scores[h][s][t] = sum_d q[s, h*64+d] * k[t, h*64+d]
    gemm_nt<<<dim3(8, 8, NH), t2>>>(pq, pk, psc, C5, C5, AD, HD, HD, C5,
                                    AD, AD, (long long)C5*C5, nullptr);
    k_softmax<<<NH*C5, 256>>>();

    // merged[s][h*64+d] = sum_t P[h][s][t] * v[t][h*64+d]
    gemm_nn<<<dim3(1, 8, NH), t2>>>(psc, pv, pm, C5, AD, C5, C5, HD, HD,
                                    (long long)C5*C5, AD, AD);

    // out[s][o] = sum_h merged[s][h] * Wout[o][h] + bout[o]
    gemm_nt<<<dim3((C6+63)/64, 8, 1), t2>>>(pm, Wout, out, C5, C6, HD, HD, HD, C6,
                                            0, 0, 0, bout);
}

// round 6
// speedup vs baseline: 1.9103x; 1.9103x over previous
#include <cuda_runtime.h>
#include <cuda_bf16.h>
#include <math.h>
#include <stdint.h>

#define N_PTS 2048
#define C_IN  512
#define KNN   40
#define C5    512
#define C6    515
#define INDIM C6
#define NKCOL (KNN*C5)         // 20480
#define HD    512
#define NH    8
#define AD    64
#define M_PAD 640              // 5*128, zero-padded rows for w6
#define SOFT_SCALE 0.04419417382415922f

// ---------------- scratch (device globals, no runtime alloc) ----------------
__device__ float g_dist[(size_t)N_PTS*N_PTS];        // 16 MB
__device__ int   g_idx[N_PTS*KNN];
__device__ float g_xx[N_PTS];
__device__ float g_At[(size_t)N_PTS*C5];
__device__ float g_Ct[(size_t)N_PTS*C5];
__device__ __nv_bfloat16 g_w6hi[(size_t)M_PAD*N_PTS];   // [o][k] K-major (zero-padded rows stay 0)
__device__ __nv_bfloat16 g_w6lo[(size_t)M_PAD*N_PTS];
__device__ __nv_bfloat16 g_Lthi[(size_t)NKCOL*N_PTS];   // [col][k] K-major (84 MB)
__device__ __nv_bfloat16 g_Ltlo[(size_t)NKCOL*N_PTS];   // 84 MB
__device__ float g_o2[(size_t)C6*NKCOL];             // 42 MB  out2[o][col]
__device__ float g_xf[C5*C6];
__device__ float g_yf[C5*C6];
__device__ float g_q [C5*HD];
__device__ float g_k [C5*HD];
__device__ float g_v [C5*HD];
__device__ float g_sc[(size_t)NH*C5*C5];
__device__ float g_mg[C5*HD];

__device__ __forceinline__ float lrelu(float v){ return v > 0.f ? v : 0.2f*v; }

// ====================== PTX helpers (all baseline sm_80+ features) ======================
__device__ __forceinline__ uint32_t smem_u32(const void* p){
    uint32_t a;
    asm("{ .reg .u64 t; cvta.to.shared.u64 t, %1; cvt.u32.u64 %0, t; }" : "=r"(a) : "l"(p));
    return a;
}
__device__ __forceinline__ void cpa16(uint32_t dst, const void* src){
    asm volatile("cp.async.cg.shared.global [%0], [%1], 16;" :: "r"(dst), "l"(src));
}
#define CPA_COMMIT() asm volatile("cp.async.commit_group;" ::: "memory")
#define CPA_WAIT1()  asm volatile("cp.async.wait_group 1;" ::: "memory")
#define CPA_WAIT0()  asm volatile("cp.async.wait_group 0;" ::: "memory")

#define LDM4(r, ad) \
    asm volatile("ldmatrix.sync.aligned.m8n8.x4.shared.b16 {%0,%1,%2,%3}, [%4];" \
        : "=r"((r)[0]), "=r"((r)[1]), "=r"((r)[2]), "=r"((r)[3]) : "r"(ad))

#define MMA_BF16(d, a, b) \
    asm volatile("mma.sync.aligned.m16n8k16.row.col.f32.bf16.bf16.f32 " \
        "{%0,%1,%2,%3},{%4,%5,%6,%7},{%8,%9},{%0,%1,%2,%3};" \
        : "+f"((d)[0]), "+f"((d)[1]), "+f"((d)[2]), "+f"((d)[3]) \
        : "r"((a)[0]), "r"((a)[1]), "r"((a)[2]), "r"((a)[3]), "r"((b)[0]), "r"((b)[1]))

// ---------------- xx[n] = sum_c x[c,n]^2 ----------------
__global__ void k_xx(const float* __restrict__ x){
    int n = blockIdx.x*blockDim.x + threadIdx.x;
    if(n < N_PTS){
        float s = 0.f;
        for(int c = 0; c < C_IN; c++){ float v = x[(size_t)c*N_PTS + n]; s += v*v; }
        g_xx[n] = s;
    }
}

// ---------------- neg sq dist (fp32, must match reference ordering) ----------------
__global__ __launch_bounds__(256) void k_dist(const float* __restrict__ x){
    __shared__ __align__(16) float sN[16][64];
    __shared__ __align__(16) float sM[16][64];
    int tx = threadIdx.x, ty = threadIdx.y, t = ty*16 + tx;
    int n0 = blockIdx.y*64, m0 = blockIdx.x*64;
    float acc[4][4] = {};
    for(int c0 = 0; c0 < C_IN; c0 += 16){
        #pragma unroll
        for(int i = 0; i < 4; i++){
            int e = t + i*256; int kt = e >> 6; int col = e & 63;
            sN[kt][col] = x[(size_t)(c0+kt)*N_PTS + n0 + col];
            sM[kt][col] = x[(size_t)(c0+kt)*N_PTS + m0 + col];
        }
        __syncthreads();
        #pragma unroll
        for(int kk = 0; kk < 16; kk++){
            float4 a4 = *(const float4*)&sN[kk][ty*4];
            float4 b4 = *(const float4*)&sM[kk][tx*4];
            float av[4] = {a4.x,a4.y,a4.z,a4.w};
            float bv[4] = {b4.x,b4.y,b4.z,b4.w};
            #pragma unroll
            for(int i = 0; i < 4; i++)
                #pragma unroll
                for(int j = 0; j < 4; j++) acc[i][j] += av[i]*bv[j];
        }
        __syncthreads();
    }
    #pragma unroll
    for(int i = 0; i < 4; i++){
        int n = n0 + ty*4 + i; float xn = g_xx[n];
        #pragma unroll
        for(int j = 0; j < 4; j++){
            int m = m0 + tx*4 + j;
            g_dist[(size_t)n*N_PTS + m] = 2.f*acc[i][j] - xn - g_xx[m];
        }
    }
}

// ---------------- top-40 per row ----------------
__global__ __launch_bounds__(256) void k_topk(){
    int n = blockIdx.x;
    __shared__ float sv[N_PTS];
    __shared__ float rv[256];
    __shared__ int   ri[256];
    int t = threadIdx.x;
    for(int i = t; i < N_PTS; i += 256) sv[i] = g_dist[(size_t)n*N_PTS + i];
    __syncthreads();
    for(int kk = 0; kk < KNN; kk++){
        float bv = -INFINITY; int bi = N_PTS;
        for(int i = t; i < N_PTS; i += 256){
            float v = sv[i];
            if(v > bv || (v == bv && i < bi)){ bv = v; bi = i; }
        }
        rv[t] = bv; ri[t] = bi; __syncthreads();
        for(int s = 128; s > 0; s >>= 1){
            if(t < s){
                float v = rv[t+s]; int i2 = ri[t+s];
                if(v > rv[t] || (v == rv[t] && i2 < ri[t])){ rv[t] = v; ri[t] = i2; }
            }
            __syncthreads();
        }
        if(t == 0){ g_idx[n*KNN + kk] = ri[0]; sv[ri[0]] = -INFINITY; }
        __syncthreads();
    }
}

// ---------------- folded conv5 ----------------
__global__ __launch_bounds__(256) void k_ac(const float* __restrict__ x, const float* __restrict__ w5,
                        const float* __restrict__ g5, const float* __restrict__ b5,
                        const float* __restrict__ m5, const float* __restrict__ v5){
    __shared__ __align__(16) float sX[16][64];
    __shared__ float sWa[64][17];
    __shared__ float sWd[64][17];
    int tx = threadIdx.x, ty = threadIdx.y, t = ty*16 + tx;
    int j0 = blockIdx.y*64, o0 = blockIdx.x*64;
    float accA[4][4] = {}, accC[4][4] = {};
    for(int c0 = 0; c0 < C_IN; c0 += 16){
        #pragma unroll
        for(int i = 0; i < 4; i++){
            int e = t + i*256; int kt = e >> 6; int col = e & 63;
            sX[kt][col] = x[(size_t)(c0+kt)*N_PTS + j0 + col];
        }
        #pragma unroll
        for(int i = 0; i < 4; i++){
            int e = t + i*256; int kt = e & 15; int oi = e >> 4;
            float wa = w5[(size_t)(o0+oi)*1024 + c0 + kt];
            float wb = w5[(size_t)(o0+oi)*1024 + 512 + c0 + kt];
            sWa[oi][kt] = wa; sWd[oi][kt] = wb - wa;
        }
        __syncthreads();
        #pragma unroll
        for(int kk = 0; kk < 16; kk++){
            float4 x4 = *(const float4*)&sX[kk][ty*4];
            float xv[4] = {x4.x,x4.y,x4.z,x4.w};
            float wa[4], wd[4];
            #pragma unroll
            for(int j = 0; j < 4; j++){ wa[j] = sWa[tx*4+j][kk]; wd[j] = sWd[tx*4+j][kk]; }
            #pragma unroll
            for(int i = 0; i < 4; i++)
                #pragma unroll
                for(int j = 0; j < 4; j++){ accA[i][j] += xv[i]*wa[j]; accC[i][j] += xv[i]*wd[j]; }
        }
        __syncthreads();
    }
    #pragma unroll
    for(int j = 0; j < 4; j++){
        int o = o0 + tx*4 + j;
        float s = g5[o]*rsqrtf(v5[o] + 1e-5f);
        float tt = b5[o] - m5[o]*s;
        #pragma unroll
        for(int i = 0; i < 4; i++){
            int jj = j0 + ty*4 + i;
            g_At[(size_t)jj*C5 + o] = s*accA[i][j];
            g_Ct[(size_t)jj*C5 + o] = s*accC[i][j] + tt;
        }
    }
}

// ---------------- w6 split to bf16 hi/lo ----------------
__global__ void k_w6split(const float* __restrict__ w6){
    int i = blockIdx.x*256 + threadIdx.x;
    if(i < C6*N_PTS){
        float v = w6[i];
        __nv_bfloat16 h = __float2bfloat16(v);
        float r = v - __bfloat162float(h);
        g_w6hi[i] = h;
        g_w6lo[i] = __float2bfloat16(r);
    }
}

// ---------------- build Lt[col][n] bf16 hi/lo (transposed, split) ----------------
__global__ __launch_bounds__(256) void k_buildLt(){
    __shared__ uint32_t sbuf[32][257];           // stride 257: conflict-free transpose
    int k  = blockIdx.x;                          // 0..39
    int n0 = blockIdx.y*32;                       // 0..2016
    int tid = threadIdx.x, wid = tid>>5, lane = tid&31;
    for(int half = 0; half < 2; half++){
        int c0 = half*256;
        #pragma unroll
        for(int q = 0; q < 4; q++){
            int nloc = wid*4 + q;
            int n = n0 + nloc;
            int j = g_idx[n*KNN + k];
            for(int c = lane; c < 256; c += 32){
                float v = g_At[(size_t)j*C5 + c0 + c] + g_Ct[(size_t)n*C5 + c0 + c];
                v = lrelu(v);
                __nv_bfloat16 h = __float2bfloat16(v);
                float r = v - __bfloat162float(h);
                __nv_bfloat16 l = __float2bfloat16(r);
                sbuf[nloc][c] = (uint32_t)__bfloat16_as_ushort(h) | ((uint32_t)__bfloat16_as_ushort(l) << 16);
            }
        }
        __syncthreads();
        for(int c = wid; c < 256; c += 8){
            uint32_t u = sbuf[lane][c];
            size_t row = (size_t)(k*C5 + c0 + c);
            g_Lthi[row*N_PTS + n0 + lane] = __ushort_as_bfloat16((unsigned short)(u & 0xFFFFu));
            g_Ltlo[row*N_PTS + n0 + lane] = __ushort_as_bfloat16((unsigned short)(u >> 16));
        }
        __syncthreads();
    }
}

// ============ warp-MMA bf16 split GEMM: o2[m][n] = sum_k w6[m][k]*L[n][k] ============
// CTA tile 128x128, K-chunk 32, 8 warps of 32x64, double-buffered cp.async.
// SMEM rows have 80-byte pitch (40 bf16): ldmatrix 8-row groups hit all 32 banks once.
#define GM_PITCHB 80                       // bytes per 32-elem row
#define GM_AOFF   0
#define GM_BOFF   20480                    // A region = 2*128*80
#define GM_STG    40960                    // per-stage bytes (A hi/lo + B hi/lo)
#define GM_SMEM   (2*GM_STG)               // 81920

__device__ __forceinline__ void gm_load_chunk(uint32_t sb, int s, int m0, int n0, int ck, int tid){
    uint32_t base = sb + s*GM_STG;
    #pragma unroll
    for(int p = 0; p < 4; p++){            // A: 1024 x 16B (hi then lo)
        int u = p*256 + tid;
        int hl = u >> 9, rem = u & 511, row = rem >> 2, seg = rem & 3;
        const __nv_bfloat16* src = (hl ? g_w6lo : g_w6hi) + (size_t)(m0+row)*N_PTS + ck*32 + seg*8;
        cpa16(base + GM_AOFF + hl*10240 + row*GM_PITCHB + seg*16, src);
    }
    #pragma unroll
    for(int p = 0; p < 4; p++){            // B: 1024 x 16B (hi then lo)
        int u = p*256 + tid;
        int hl = u >> 9, rem = u & 511, row = rem >> 2, seg = rem & 3;
        const __nv_bfloat16* src = (hl ? g_Ltlo : g_Lthi) + (size_t)(n0+row)*N_PTS + ck*32 + seg*8;
        cpa16(base + GM_BOFF + hl*10240 + row*GM_PITCHB + seg*16, src);
    }
}

__global__ void __launch_bounds__(256, 1) gemm_mma(){
    extern __shared__ __align__(128) char smem[];
    uint32_t sb = smem_u32(smem);
    int tid = threadIdx.x, lane = tid & 31, wid = tid >> 5;
    int wm = wid & 3, wn = wid >> 2;       // 4 x 2 warp grid -> warp tile 32x64
    int m0 = blockIdx.x*128, n0 = blockIdx.y*128;

    float acc[2][8][4];
    #pragma unroll
    for(int i = 0; i < 2; i++)
        #pragma unroll
        for(int j = 0; j < 8; j++)
            #pragma unroll
            for(int q = 0; q < 4; q++) acc[i][j][q] = 0.f;

    gm_load_chunk(sb, 0, m0, n0, 0, tid);
    CPA_COMMIT();

    // fragment address components (constant across chunks)
    int a_row = wm*32 + (lane & 15);              // + mt*16
    int a_col2 = ((lane >> 4) * 8) * 2;           // + kb*2
    int b_row = wn*64 + (lane & 7) + ((lane >> 4) << 3);   // + np*16
    int b_col2 = (((lane >> 3) & 1) * 8) * 2;     // + kb*2

    for(int c = 0; c < 64; c++){
        if(c + 1 < 64){
            gm_load_chunk(sb, (c+1)&1, m0, n0, c+1, tid);
            CPA_COMMIT();
            CPA_WAIT1();
        } else {
            CPA_WAIT0();
        }
        __syncthreads();

        uint32_t base = sb + (c&1)*GM_STG;
        #pragma unroll
        for(int h = 0; h < 2; h++){
            int kb2 = h*16*2;
            uint32_t ah[2][4], al[2][4];
            #pragma unroll
            for(int mt = 0; mt < 2; mt++){
                uint32_t ad = base + GM_AOFF + (a_row + mt*16)*GM_PITCHB + a_col2 + kb2;
                LDM4(ah[mt], ad);
                LDM4(al[mt], ad + 10240);
            }
            uint32_t bh[8][2], bl[8][2];
            #pragma unroll
            for(int np = 0; np < 4; np++){
                uint32_t bd = base + GM_BOFF + (b_row + np*16)*GM_PITCHB + b_col2 + kb2;
                uint32_t r[4];
                LDM4(r, bd);
                bh[np*2][0] = r[0]; bh[np*2][1] = r[1]; bh[np*2+1][0] = r[2]; bh[np*2+1][1] = r[3];
                LDM4(r, bd + 10240);
                bl[np*2][0] = r[0]; bl[np*2][1] = r[1]; bl[np*2+1][0] = r[2]; bl[np*2+1][1] = r[3];
            }
            #pragma unroll
            for(int mt = 0; mt < 2; mt++)
                #pragma unroll
                for(int nt = 0; nt < 8; nt++){
                    MMA_BF16(acc[mt][nt], ah[mt], bh[nt]);
                    MMA_BF16(acc[mt][nt], ah[mt], bl[nt]);
                    MMA_BF16(acc[mt][nt], al[mt], bh[nt]);
                }
        }
        __syncthreads();
    }

    // epilogue: d-frag thread mapping g=lane>>2 (rows g, g+8), tg=lane&3 (cols tg*2,+1)
    int g = lane >> 2, tg = lane & 3;
    #pragma unroll
    for(int mt = 0; mt < 2; mt++){
        int m = m0 + wm*32 + mt*16 + g;
        #pragma unroll
        for(int nt = 0; nt < 8; nt++){
            int col = n0 + wn*64 + nt*8 + tg*2;
            if(m < C6)
                *(float2*)(g_o2 + (size_t)m*NKCOL + col) = make_float2(acc[mt][nt][0], acc[mt][nt][1]);
            if(m + 8 < C6)
                *(float2*)(g_o2 + (size_t)(m+8)*NKCOL + col) = make_float2(acc[mt][nt][2], acc[mt][nt][3]);
        }
    }
}

// ---------------- generic gemm_nn (attention tail) ----------------
__global__ __launch_bounds__(256) void gemm_nn(const float* __restrict__ A, const float* __restrict__ B,
                       float* __restrict__ C, int M, int N, int K,
                       int lda, int ldb, int ldc,
                       long long sA, long long sB, long long sC){
    A += (size_t)blockIdx.z * sA; B += (size_t)blockIdx.z * sB; C += (size_t)blockIdx.z * sC;
    __shared__ float sAp[64][17];
    __shared__ __align__(16) float sBt[16][64];
    int tx = threadIdx.x, ty = threadIdx.y, t = ty*16 + tx;
    int m0 = blockIdx.y*64, n0 = blockIdx.x*64;
    float acc[4][4] = {};
    for(int k0 = 0; k0 < K; k0 += 16){
        #pragma unroll
        for(int i = 0; i < 4; i++){
            int e = t + i*256; int kt = e & 15; int mi = e >> 4;
            int m = m0 + mi, k = k0 + kt;
            sAp[mi][kt] = (m < M && k < K) ? A[(size_t)m*lda + k] : 0.f;
        }
        #pragma unroll
        for(int i = 0; i < 4; i++){
            int e = t + i*256; int ni = e & 63; int kt = e >> 6;
            int k = k0 + kt, n = n0 + ni;
            sBt[kt][ni] = (k < K && n < N) ? B[(size_t)k*ldb + n] : 0.f;
        }
        __syncthreads();
        #pragma unroll
        for(int kk = 0; kk < 16; kk++){
            float av[4];
            #pragma unroll
            for(int i = 0; i < 4; i++) av[i] = sAp[ty*4+i][kk];
            float4 b4 = *(const float4*)&sBt[kk][tx*4];
            float bv[4] = {b4.x,b4.y,b4.z,b4.w};
            #pragma unroll
            for(int i = 0; i < 4; i++)
                #pragma unroll
                for(int j = 0; j < 4; j++) acc[i][j] += av[i]*bv[j];
        }
        __syncthreads();
    }
    #pragma unroll
    for(int i = 0; i < 4; i++){
        int m = m0 + ty*4 + i; if(m >= M) continue;
        #pragma unroll
        for(int j = 0; j < 4; j++){
            int n = n0 + tx*4 + j; if(n >= N) continue;
            C[(size_t)m*ldc + n] = acc[i][j];
        }
    }
}

// ---------------- generic gemm_nt (+bias) ----------------
__global__ __launch_bounds__(256) void gemm_nt(const float* __restrict__ A, const float* __restrict__ B,
                       float* __restrict__ C, int M, int N, int K,
                       int lda, int ldb, int ldc,
                       long long sA, long long sB, long long sC,
                       const float* __restrict__ bias){
    A += (size_t)blockIdx.z * sA; B += (size_t)blockIdx.z * sB; C += (size_t)blockIdx.z * sC;
    __shared__ float sAp[64][17];
    __shared__ float sBp[64][17];
    int tx = threadIdx.x, ty = threadIdx.y, t = ty*16 + tx;
    int m0 = blockIdx.y*64, n0 = blockIdx.x*64;
    float acc[4][4] = {};
    for(int k0 = 0; k0 < K; k0 += 16){
        #pragma unroll
        for(int i = 0; i < 4; i++){
            int e = t + i*256; int kt = e & 15; int mi = e >> 4;
            int m = m0 + mi, k = k0 + kt;
            sAp[mi][kt] = (m < M && k < K) ? A[(size_t)m*lda + k] : 0.f;
        }
        #pragma unroll
        for(int i = 0; i < 4; i++){
            int e = t + i*256; int kt = e & 15; int ni = e >> 4;
            int n = n0 + ni, k = k0 + kt;
            sBp[ni][kt] = (n < N && k < K) ? B[(size_t)n*ldb + k] : 0.f;
        }
        __syncthreads();
        #pragma unroll
        for(int kk = 0; kk < 16; kk++){
            float av[4], bv[4];
            #pragma unroll
            for(int i = 0; i < 4; i++) av[i] = sAp[ty*4+i][kk];
            #pragma unroll
            for(int j = 0; j < 4; j++) bv[j] = sBp[tx*4+j][kk];
            #pragma unroll
            for(int i = 0; i < 4; i++)
                #pragma unroll
                for(int j = 0; j < 4; j++) acc[i][j] += av[i]*bv[j];
        }
        __syncthreads();
    }
    #pragma unroll
    for(int i = 0; i < 4; i++){
        int m = m0 + ty*4 + i; if(m >= M) continue;
        #pragma unroll
        for(int j = 0; j < 4; j++){
            int n = n0 + tx*4 + j; if(n >= N) continue;
            float bb = bias ? bias[n] : 0.f;
            C[(size_t)m*ldc + n] = acc[i][j] + bb;
        }
    }
}

// ---------------- bn6 + lrelu + max over k ----------------
__global__ void k_maxpool(const float* __restrict__ g6, const float* __restrict__ b6,
                          const float* __restrict__ m6, const float* __restrict__ v6,
                          float* __restrict__ f){
    int o = blockIdx.y;
    int c = blockIdx.x*256 + threadIdx.x;
    float s = g6[o]*rsqrtf(v6[o] + 1e-5f);
    float t = b6[o] - m6[o]*s;
    const float* row = g_o2 + (size_t)o*NKCOL + c;
    float mx = -INFINITY;
    #pragma unroll 8
    for(int k = 0; k < KNN; k++){
        float h = s*row[(size_t)k*C5] + t;
        h = lrelu(h);
        mx = fmaxf(mx, h);
    }
    f[(size_t)c*C6 + o] = mx;
}

// ---------------- row softmax ----------------
__global__ __launch_bounds__(256) void k_softmax(){
    int r = blockIdx.x;
    float* p = g_sc + (size_t)r*C5;
    __shared__ float red[256];
    int t = threadIdx.x;
    float v0 = p[t]*SOFT_SCALE, v1 = p[t+256]*SOFT_SCALE;
    red[t] = fmaxf(v0, v1); __syncthreads();
    for(int s = 128; s > 0; s >>= 1){ if(t < s) red[t] = fmaxf(red[t], red[t+s]); __syncthreads(); }
    float mm = red[0]; __syncthreads();
    float e0 = __expf(v0 - mm), e1 = __expf(v1 - mm);
    red[t] = e0 + e1; __syncthreads();
    for(int s = 128; s > 0; s >>= 1){ if(t < s) red[t] += red[t+s]; __syncthreads(); }
    float inv = 1.f/red[0];
    p[t] = e0*inv; p[t+256] = e1*inv;
}

// =============================== host launcher ===============================
extern "C" void kernel_launch(void* const* d_in, const int* in_sizes, int n_in,
                              void* d_out, int out_size){
    const float* x    = (const float*)d_in[0];
    const float* y    = (const float*)d_in[1];
    const float* w5   = (const float*)d_in[2];
    const float* g5   = (const float*)d_in[3];
    const float* b5   = (const float*)d_in[4];
    const float* m5   = (const float*)d_in[5];
    const float* v5   = (const float*)d_in[6];
    const float* w6   = (const float*)d_in[7];
    const float* g6   = (const float*)d_in[8];
    const float* b6   = (const float*)d_in[9];
    const float* m6   = (const float*)d_in[10];
    const float* v6   = (const float*)d_in[11];
    const float* Wq   = (const float*)d_in[12];
    const float* Wk   = (const float*)d_in[13];
    const float* Wv   = (const float*)d_in[14];
    const float* Wout = (const float*)d_in[15];
    const float* bout = (const float*)d_in[16];
    float* out = (float*)d_out;

    float *pxf, *pyf, *pq, *pk, *pv, *psc, *pm;
    cudaGetSymbolAddress((void**)&pxf, g_xf);
    cudaGetSymbolAddress((void**)&pyf, g_yf);
    cudaGetSymbolAddress((void**)&pq,  g_q);
    cudaGetSymbolAddress((void**)&pk,  g_k);
    cudaGetSymbolAddress((void**)&pv,  g_v);
    cudaGetSymbolAddress((void**)&psc, g_sc);
    cudaGetSymbolAddress((void**)&pm,  g_mg);

    cudaFuncSetAttribute(gemm_mma, cudaFuncAttributeMaxDynamicSharedMemorySize, GM_SMEM);

    dim3 t2(16, 16);

    k_w6split<<<(C6*N_PTS + 255)/256, 256>>>(w6);

    for(int br = 0; br < 2; br++){
        const float* p = br ? y : x;
        float* f = br ? pyf : pxf;

        k_xx<<<8, 256>>>(p);
        k_dist<<<dim3(32, 32), t2>>>(p);
        k_topk<<<N_PTS, 256>>>();
        k_ac<<<dim3(8, 32), t2>>>(p, w5, g5, b5, m5, v5);
        k_buildLt<<<dim3(KNN, 64), 256>>>();
        gemm_mma<<<dim3(5, 160), 256, GM_SMEM>>>();
        k_maxpool<<<dim3(2, C6), 256>>>(g6, b6, m6, v6, f);
    }

    // q/k/v
    gemm_nt<<<dim3(8, 8, 1), t2>>>(pxf, Wq, pq, C5, HD, INDIM, INDIM, INDIM, HD, 0, 0, 0, nullptr);
    gemm_nt<<<dim3(8, 8, 1), t2>>>(pyf, Wk, pk, C5, HD, INDIM, INDIM, INDIM, HD, 0, 0, 0, nullptr);
    gemm_nt<<<dim3(8, 8, 1), t2>>>(pyf, Wv, pv, C5, HD, INDIM, INDIM, INDIM, HD, 0, 0, 0, nullptr);

    // scores
    gemm_nt<<<dim3(8, 8, NH), t2>>>(pq, pk, psc, C5, C5, AD, HD, HD, C5,
                                    AD, AD, (long long)C5*C5, nullptr);
    k_softmax<<<NH*C5, 256>>>();

    // weighted
    gemm_nn<<<dim3(1, 8, NH), t2>>>(psc, pv, pm, C5, AD, C5, C5, HD, HD,
                                    (long long)C5*C5, AD, AD);

    // output projection
    gemm_nt<<<dim3((C6+63)/64, 8, 1), t2>>>(pm, Wout, out, C5, C6, HD, HD, HD, C6,
                                            0, 0, 0, bout);
}

// round 8
// speedup vs baseline: 2.1295x; 1.1147x over previous
#include <cuda_runtime.h>
#include <cuda_bf16.h>
#include <math.h>
#include <stdint.h>

#define N_PTS 2048
#define C_IN  512
#define KNN   40
#define C5    512
#define C6    515
#define INDIM C6
#define NKCOL (KNN*C5)         // 20480
#define HD    512
#define NH    8
#define AD    64
#define M_PAD 640              // 5*128, zero-padded rows for w6
#define SOFT_SCALE 0.04419417382415922f

// ---------------- scratch (device globals, no runtime alloc) ----------------
__device__ float g_dist[(size_t)N_PTS*N_PTS];        // 16 MB
__device__ int   g_idx[N_PTS*KNN];
__device__ float g_xx[N_PTS];
__device__ float g_At[(size_t)N_PTS*C5];
__device__ float g_Ct[(size_t)N_PTS*C5];
__device__ __nv_bfloat16 g_w6hi[(size_t)M_PAD*N_PTS];   // [o][k] K-major (zero-padded rows stay 0)
__device__ __nv_bfloat16 g_w6lo[(size_t)M_PAD*N_PTS];
__device__ __nv_bfloat16 g_Lthi[(size_t)NKCOL*N_PTS];   // [col][k] K-major (84 MB)
__device__ __nv_bfloat16 g_Ltlo[(size_t)NKCOL*N_PTS];   // 84 MB
__device__ float g_o2[(size_t)C6*NKCOL];             // 42 MB  out2[o][col]
__device__ float g_xf[C5*C6];
__device__ float g_yf[C5*C6];
__device__ float g_q [C5*HD];
__device__ float g_k [C5*HD];
__device__ float g_v [C5*HD];
__device__ float g_sc[(size_t)NH*C5*C5];
__device__ float g_mg[C5*HD];

__device__ __forceinline__ float lrelu(float v){ return v > 0.f ? v : 0.2f*v; }

// ====================== PTX helpers (all baseline sm_80+ features) ======================
__device__ __forceinline__ uint32_t smem_u32(const void* p){
    uint32_t a;
    asm("{ .reg .u64 t; cvta.to.shared.u64 t, %1; cvt.u32.u64 %0, t; }" : "=r"(a) : "l"(p));
    return a;
}
__device__ __forceinline__ void cpa16(uint32_t dst, const void* src){
    asm volatile("cp.async.cg.shared.global [%0], [%1], 16;" :: "r"(dst), "l"(src));
}
#define CPA_COMMIT() asm volatile("cp.async.commit_group;" ::: "memory")
#define CPA_WAIT1()  asm volatile("cp.async.wait_group 1;" ::: "memory")
#define CPA_WAIT0()  asm volatile("cp.async.wait_group 0;" ::: "memory")

#define LDM4(r, ad) \
    asm volatile("ldmatrix.sync.aligned.m8n8.x4.shared.b16 {%0,%1,%2,%3}, [%4];" \
        : "=r"((r)[0]), "=r"((r)[1]), "=r"((r)[2]), "=r"((r)[3]) : "r"(ad))

#define MMA_BF16(d, a, b) \
    asm volatile("mma.sync.aligned.m16n8k16.row.col.f32.bf16.bf16.f32 " \
        "{%0,%1,%2,%3},{%4,%5,%6,%7},{%8,%9},{%0,%1,%2,%3};" \
        : "+f"((d)[0]), "+f"((d)[1]), "+f"((d)[2]), "+f"((d)[3]) \
        : "r"((a)[0]), "r"((a)[1]), "r"((a)[2]), "r"((a)[3]), "r"((b)[0]), "r"((b)[1]))

// ---------------- xx[n] = sum_c x[c,n]^2 ----------------
__global__ void k_xx(const float* __restrict__ x){
    int n = blockIdx.x*blockDim.x + threadIdx.x;
    if(n < N_PTS){
        float s = 0.f;
        for(int c = 0; c < C_IN; c++){ float v = x[(size_t)c*N_PTS + n]; s += v*v; }
        g_xx[n] = s;
    }
}

// ---------------- neg sq dist (fp32, must match reference ordering) ----------------
__global__ __launch_bounds__(256) void k_dist(const float* __restrict__ x){
    __shared__ __align__(16) float sN[16][64];
    __shared__ __align__(16) float sM[16][64];
    int tx = threadIdx.x, ty = threadIdx.y, t = ty*16 + tx;
    int n0 = blockIdx.y*64, m0 = blockIdx.x*64;
    float acc[4][4] = {};
    for(int c0 = 0; c0 < C_IN; c0 += 16){
        #pragma unroll
        for(int i = 0; i < 4; i++){
            int e = t + i*256; int kt = e >> 6; int col = e & 63;
            sN[kt][col] = x[(size_t)(c0+kt)*N_PTS + n0 + col];
            sM[kt][col] = x[(size_t)(c0+kt)*N_PTS + m0 + col];
        }
        __syncthreads();
        #pragma unroll
        for(int kk = 0; kk < 16; kk++){
            float4 a4 = *(const float4*)&sN[kk][ty*4];
            float4 b4 = *(const float4*)&sM[kk][tx*4];
            float av[4] = {a4.x,a4.y,a4.z,a4.w};
            float bv[4] = {b4.x,b4.y,b4.z,b4.w};
            #pragma unroll
            for(int i = 0; i < 4; i++)
                #pragma unroll
                for(int j = 0; j < 4; j++) acc[i][j] += av[i]*bv[j];
        }
        __syncthreads();
    }
    #pragma unroll
    for(int i = 0; i < 4; i++){
        int n = n0 + ty*4 + i; float xn = g_xx[n];
        #pragma unroll
        for(int j = 0; j < 4; j++){
            int m = m0 + tx*4 + j;
            g_dist[(size_t)n*N_PTS + m] = 2.f*acc[i][j] - xn - g_xx[m];
        }
    }
}

// ---------------- top-40 per row: 4-pass radix select + exact jax ordering ----------------
// order-preserving map: u = (b & sign) ? ~b : b | sign   (bigger float -> bigger uint)
__global__ __launch_bounds__(256) void k_topk(){
    __shared__ int hist[256];
    __shared__ int s_nextb, s_nextneed;
    __shared__ int s_cnt, s_eqcnt;
    __shared__ uint32_t s_selu[KNN];
    __shared__ int      s_seli[KNN];
    __shared__ int      s_eq[64];

    int n = blockIdx.x;
    int t = threadIdx.x;
    const float* row = g_dist + (size_t)n*N_PTS;

    uint32_t u[8];
    #pragma unroll
    for(int i = 0; i < 8; i++){
        uint32_t b = __float_as_uint(row[t + 256*i]);
        u[i] = (b & 0x80000000u) ? ~b : (b | 0x80000000u);
    }

    uint32_t prefix = 0, mask = 0;
    int need = KNN;
    #pragma unroll
    for(int pass = 0; pass < 4; pass++){
        int shift = 24 - pass*8;
        hist[t] = 0;
        __syncthreads();
        #pragma unroll
        for(int i = 0; i < 8; i++)
            if((u[i] & mask) == prefix) atomicAdd(&hist[(u[i] >> shift) & 0xFF], 1);
        __syncthreads();
        // inclusive suffix scan (Hillis-Steele, double-sync)
        int v = hist[t];
        for(int off = 1; off < 256; off <<= 1){
            int w = (t + off < 256) ? hist[t + off] : 0;
            __syncthreads();
            v += w; hist[t] = v;
            __syncthreads();
        }
        // boundary bucket: S[b] >= need, S[b+1] < need
        int Sn = (t < 255) ? hist[t + 1] : 0;
        if(v >= need && Sn < need){ s_nextb = t; s_nextneed = need - Sn; }
        __syncthreads();
        prefix |= ((uint32_t)s_nextb) << shift;
        mask   |= 0xFFu << shift;
        need = s_nextneed;
        __syncthreads();
    }
    // prefix == exact u-value of the 40th largest; need == count to take among equals
    if(t == 0){ s_cnt = 0; s_eqcnt = 0; }
    __syncthreads();
    #pragma unroll
    for(int i = 0; i < 8; i++){
        if(u[i] > prefix){
            int p = atomicAdd(&s_cnt, 1);
            s_selu[p] = u[i]; s_seli[p] = t + 256*i;
        } else if(u[i] == prefix){
            int p = atomicAdd(&s_eqcnt, 1);
            if(p < 64) s_eq[p] = t + 256*i;
        }
    }
    __syncthreads();
    // fill ties: smallest indices first (jax tie-break)
    if(t == 0){
        int cnt = s_cnt;
        int e = s_eqcnt < 64 ? s_eqcnt : 64;
        for(int j = 0; j < need; j++){
            int best = 0x7FFFFFFF, bi = -1;
            for(int q = 0; q < e; q++)
                if(s_eq[q] < best){ best = s_eq[q]; bi = q; }
            s_selu[cnt + j] = prefix; s_seli[cnt + j] = best;
            s_eq[bi] = 0x7FFFFFFF;
        }
    }
    __syncthreads();
    // exact jax order: rank by (value desc, index asc)
    if(t < KNN){
        uint32_t mu = s_selu[t]; int mi = s_seli[t];
        int rank = 0;
        #pragma unroll
        for(int q = 0; q < KNN; q++){
            uint32_t qu = s_selu[q]; int qi = s_seli[q];
            rank += (qu > mu) || (qu == mu && qi < mi);
        }
        g_idx[n*KNN + rank] = mi;
    }
}

// ---------------- folded conv5 ----------------
__global__ __launch_bounds__(256) void k_ac(const float* __restrict__ x, const float* __restrict__ w5,
                        const float* __restrict__ g5, const float* __restrict__ b5,
                        const float* __restrict__ m5, const float* __restrict__ v5){
    __shared__ __align__(16) float sX[16][64];
    __shared__ float sWa[64][17];
    __shared__ float sWd[64][17];
    int tx = threadIdx.x, ty = threadIdx.y, t = ty*16 + tx;
    int j0 = blockIdx.y*64, o0 = blockIdx.x*64;
    float accA[4][4] = {}, accC[4][4] = {};
    for(int c0 = 0; c0 < C_IN; c0 += 16){
        #pragma unroll
        for(int i = 0; i < 4; i++){
            int e = t + i*256; int kt = e >> 6; int col = e & 63;
            sX[kt][col] = x[(size_t)(c0+kt)*N_PTS + j0 + col];
        }
        #pragma unroll
        for(int i = 0; i < 4; i++){
            int e = t + i*256; int kt = e & 15; int oi = e >> 4;
            float wa = w5[(size_t)(o0+oi)*1024 + c0 + kt];
            float wb = w5[(size_t)(o0+oi)*1024 + 512 + c0 + kt];
            sWa[oi][kt] = wa; sWd[oi][kt] = wb - wa;
        }
        __syncthreads();
        #pragma unroll
        for(int kk = 0; kk < 16; kk++){
            float4 x4 = *(const float4*)&sX[kk][ty*4];
            float xv[4] = {x4.x,x4.y,x4.z,x4.w};
            float wa[4], wd[4];
            #pragma unroll
            for(int j = 0; j < 4; j++){ wa[j] = sWa[tx*4+j][kk]; wd[j] = sWd[tx*4+j][kk]; }
            #pragma unroll
            for(int i = 0; i < 4; i++)
                #pragma unroll
                for(int j = 0; j < 4; j++){ accA[i][j] += xv[i]*wa[j]; accC[i][j] += xv[i]*wd[j]; }
        }
        __syncthreads();
    }
    #pragma unroll
    for(int j = 0; j < 4; j++){
        int o = o0 + tx*4 + j;
        float s = g5[o]*rsqrtf(v5[o] + 1e-5f);
        float tt = b5[o] - m5[o]*s;
        #pragma unroll
        for(int i = 0; i < 4; i++){
            int jj = j0 + ty*4 + i;
            g_At[(size_t)jj*C5 + o] = s*accA[i][j];
            g_Ct[(size_t)jj*C5 + o] = s*accC[i][j] + tt;
        }
    }
}

// ---------------- w6 split to bf16 hi/lo ----------------
__global__ void k_w6split(const float* __restrict__ w6){
    int i = blockIdx.x*256 + threadIdx.x;
    if(i < C6*N_PTS){
        float v = w6[i];
        __nv_bfloat16 h = __float2bfloat16(v);
        float r = v - __bfloat162float(h);
        g_w6hi[i] = h;
        g_w6lo[i] = __float2bfloat16(r);
    }
}

// ---------------- build Lt[col][n] bf16 hi/lo (transposed, split) ----------------
__global__ __launch_bounds__(256) void k_buildLt(){
    __shared__ uint32_t sbuf[32][257];           // stride 257: conflict-free transpose
    int k  = blockIdx.x;                          // 0..39
    int n0 = blockIdx.y*32;                       // 0..2016
    int tid = threadIdx.x, wid = tid>>5, lane = tid&31;
    for(int half = 0; half < 2; half++){
        int c0 = half*256;
        #pragma unroll
        for(int q = 0; q < 4; q++){
            int nloc = wid*4 + q;
            int n = n0 + nloc;
            int j = g_idx[n*KNN + k];
            for(int c = lane; c < 256; c += 32){
                float v = g_At[(size_t)j*C5 + c0 + c] + g_Ct[(size_t)n*C5 + c0 + c];
                v = lrelu(v);
                __nv_bfloat16 h = __float2bfloat16(v);
                float r = v - __bfloat162float(h);
                __nv_bfloat16 l = __float2bfloat16(r);
                sbuf[nloc][c] = (uint32_t)__bfloat16_as_ushort(h) | ((uint32_t)__bfloat16_as_ushort(l) << 16);
            }
        }
        __syncthreads();
        for(int c = wid; c < 256; c += 8){
            uint32_t u = sbuf[lane][c];
            size_t row = (size_t)(k*C5 + c0 + c);
            g_Lthi[row*N_PTS + n0 + lane] = __ushort_as_bfloat16((unsigned short)(u & 0xFFFFu));
            g_Ltlo[row*N_PTS + n0 + lane] = __ushort_as_bfloat16((unsigned short)(u >> 16));
        }
        __syncthreads();
    }
}

// ============ warp-MMA bf16 split GEMM: o2[m][n] = sum_k w6[m][k]*L[n][k] ============
// CTA tile 128x128, K-chunk 32, 8 warps of 32x64, double-buffered cp.async.
// SMEM rows have 80-byte pitch (40 bf16): ldmatrix 8-row groups hit all 32 banks once.
#define GM_PITCHB 80                       // bytes per 32-elem row
#define GM_AOFF   0
#define GM_BOFF   20480                    // A region = 2*128*80
#define GM_STG    40960                    // per-stage bytes (A hi/lo + B hi/lo)
#define GM_SMEM   (2*GM_STG)               // 81920

__device__ __forceinline__ void gm_load_chunk(uint32_t sb, int s, int m0, int n0, int ck, int tid){
    uint32_t base = sb + s*GM_STG;
    #pragma unroll
    for(int p = 0; p < 4; p++){            // A: 1024 x 16B (hi then lo)
        int u = p*256 + tid;
        int hl = u >> 9, rem = u & 511, row = rem >> 2, seg = rem & 3;
        const __nv_bfloat16* src = (hl ? g_w6lo : g_w6hi) + (size_t)(m0+row)*N_PTS + ck*32 + seg*8;
        cpa16(base + GM_AOFF + hl*10240 + row*GM_PITCHB + seg*16, src);
    }
    #pragma unroll
    for(int p = 0; p < 4; p++){            // B: 1024 x 16B (hi then lo)
        int u = p*256 + tid;
        int hl = u >> 9, rem = u & 511, row = rem >> 2, seg = rem & 3;
        const __nv_bfloat16* src = (hl ? g_Ltlo : g_Lthi) + (size_t)(n0+row)*N_PTS + ck*32 + seg*8;
        cpa16(base + GM_BOFF + hl*10240 + row*GM_PITCHB + seg*16, src);
    }
}

__global__ void __launch_bounds__(256, 1) gemm_mma(){
    extern __shared__ __align__(128) char smem[];
    uint32_t sb = smem_u32(smem);
    int tid = threadIdx.x, lane = tid & 31, wid = tid >> 5;
    int wm = wid & 3, wn = wid >> 2;       // 4 x 2 warp grid -> warp tile 32x64
    int m0 = blockIdx.x*128, n0 = blockIdx.y*128;

    float acc[2][8][4];
    #pragma unroll
    for(int i = 0; i < 2; i++)
        #pragma unroll
        for(int j = 0; j < 8; j++)
            #pragma unroll
            for(int q = 0; q < 4; q++) acc[i][j][q] = 0.f;

    gm_load_chunk(sb, 0, m0, n0, 0, tid);
    CPA_COMMIT();

    // fragment address components (constant across chunks)
    int a_row = wm*32 + (lane & 15);              // + mt*16
    int a_col2 = ((lane >> 4) * 8) * 2;           // + kb*2
    int b_row = wn*64 + (lane & 7) + ((lane >> 4) << 3);   // + np*16
    int b_col2 = (((lane >> 3) & 1) * 8) * 2;     // + kb*2

    for(int c = 0; c < 64; c++){
        if(c + 1 < 64){
            gm_load_chunk(sb, (c+1)&1, m0, n0, c+1, tid);
            CPA_COMMIT();
            CPA_WAIT1();
        } else {
            CPA_WAIT0();
        }
        __syncthreads();

        uint32_t base = sb + (c&1)*GM_STG;
        #pragma unroll
        for(int h = 0; h < 2; h++){
            int kb2 = h*16*2;
            uint32_t ah[2][4], al[2][4];
            #pragma unroll
            for(int mt = 0; mt < 2; mt++){
                uint32_t ad = base + GM_AOFF + (a_row + mt*16)*GM_PITCHB + a_col2 + kb2;
                LDM4(ah[mt], ad);
                LDM4(al[mt], ad + 10240);
            }
            uint32_t bh[8][2], bl[8][2];
            #pragma unroll
            for(int np = 0; np < 4; np++){
                uint32_t bd = base + GM_BOFF + (b_row + np*16)*GM_PITCHB + b_col2 + kb2;
                uint32_t r[4];
                LDM4(r, bd);
                bh[np*2][0] = r[0]; bh[np*2][1] = r[1]; bh[np*2+1][0] = r[2]; bh[np*2+1][1] = r[3];
                LDM4(r, bd + 10240);
                bl[np*2][0] = r[0]; bl[np*2][1] = r[1]; bl[np*2+1][0] = r[2]; bl[np*2+1][1] = r[3];
            }
            #pragma unroll
            for(int mt = 0; mt < 2; mt++)
                #pragma unroll
                for(int nt = 0; nt < 8; nt++){
                    MMA_BF16(acc[mt][nt], ah[mt], bh[nt]);
                    MMA_BF16(acc[mt][nt], ah[mt], bl[nt]);
                    MMA_BF16(acc[mt][nt], al[mt], bh[nt]);
                }
        }
        __syncthreads();
    }

    // epilogue: d-frag thread mapping g=lane>>2 (rows g, g+8), tg=lane&3 (cols tg*2,+1)
    int g = lane >> 2, tg = lane & 3;
    #pragma unroll
    for(int mt = 0; mt < 2; mt++){
        int m = m0 + wm*32 + mt*16 + g;
        #pragma unroll
        for(int nt = 0; nt < 8; nt++){
            int col = n0 + wn*64 + nt*8 + tg*2;
            if(m < C6)
                *(float2*)(g_o2 + (size_t)m*NKCOL + col) = make_float2(acc[mt][nt][0], acc[mt][nt][1]);
            if(m + 8 < C6)
                *(float2*)(g_o2 + (size_t)(m+8)*NKCOL + col) = make_float2(acc[mt][nt][2], acc[mt][nt][3]);
        }
    }
}

// ---------------- generic gemm_nn (attention tail) ----------------
__global__ __launch_bounds__(256) void gemm_nn(const float* __restrict__ A, const float* __restrict__ B,
                       float* __restrict__ C, int M, int N, int K,
                       int lda, int ldb, int ldc,
                       long long sA, long long sB, long long sC){
    A += (size_t)blockIdx.z * sA; B += (size_t)blockIdx.z * sB; C += (size_t)blockIdx.z * sC;
    __shared__ float sAp[64][17];
    __shared__ __align__(16) float sBt[16][64];
    int tx = threadIdx.x, ty = threadIdx.y, t = ty*16 + tx;
    int m0 = blockIdx.y*64, n0 = blockIdx.x*64;
    float acc[4][4] = {};
    for(int k0 = 0; k0 < K; k0 += 16){
        #pragma unroll
        for(int i = 0; i < 4; i++){
            int e = t + i*256; int kt = e & 15; int mi = e >> 4;
            int m = m0 + mi, k = k0 + kt;
            sAp[mi][kt] = (m < M && k < K) ? A[(size_t)m*lda + k] : 0.f;
        }
        #pragma unroll
        for(int i = 0; i < 4; i++){
            int e = t + i*256; int ni = e & 63; int kt = e >> 6;
            int k = k0 + kt, n = n0 + ni;
            sBt[kt][ni] = (k < K && n < N) ? B[(size_t)k*ldb + n] : 0.f;
        }
        __syncthreads();
        #pragma unroll
        for(int kk = 0; kk < 16; kk++){
            float av[4];
            #pragma unroll
            for(int i = 0; i < 4; i++) av[i] = sAp[ty*4+i][kk];
            float4 b4 = *(const float4*)&sBt[kk][tx*4];
            float bv[4] = {b4.x,b4.y,b4.z,b4.w};
            #pragma unroll
            for(int i = 0; i < 4; i++)
                #pragma unroll
                for(int j = 0; j < 4; j++) acc[i][j] += av[i]*bv[j];
        }
        __syncthreads();
    }
    #pragma unroll
    for(int i = 0; i < 4; i++){
        int m = m0 + ty*4 + i; if(m >= M) continue;
        #pragma unroll
        for(int j = 0; j < 4; j++){
            int n = n0 + tx*4 + j; if(n >= N) continue;
            C[(size_t)m*ldc + n] = acc[i][j];
        }
    }
}

// ---------------- generic gemm_nt (+bias) ----------------
__global__ __launch_bounds__(256) void gemm_nt(const float* __restrict__ A, const float* __restrict__ B,
                       float* __restrict__ C, int M, int N, int K,
                       int lda, int ldb, int ldc,
                       long long sA, long long sB, long long sC,
                       const float* __restrict__ bias){
    A += (size_t)blockIdx.z * sA; B += (size_t)blockIdx.z * sB; C += (size_t)blockIdx.z * sC;
    __shared__ float sAp[64][17];
    __shared__ float sBp[64][17];
    int tx = threadIdx.x, ty = threadIdx.y, t = ty*16 + tx;
    int m0 = blockIdx.y*64, n0 = blockIdx.x*64;
    float acc[4][4] = {};
    for(int k0 = 0; k0 < K; k0 += 16){
        #pragma unroll
        for(int i = 0; i < 4; i++){
            int e = t + i*256; int kt = e & 15; int mi = e >> 4;
            int m = m0 + mi, k = k0 + kt;
            sAp[mi][kt] = (m < M && k < K) ? A[(size_t)m*lda + k] : 0.f;
        }
        #pragma unroll
        for(int i = 0; i < 4; i++){
            int e = t + i*256; int kt = e & 15; int ni = e >> 4;
            int n = n0 + ni, k = k0 + kt;
            sBp[ni][kt] = (n < N && k < K) ? B[(size_t)n*ldb + k] : 0.f;
        }
        __syncthreads();
        #pragma unroll
        for(int kk = 0; kk < 16; kk++){
            float av[4], bv[4];
            #pragma unroll
            for(int i = 0; i < 4; i++) av[i] = sAp[ty*4+i][kk];
            #pragma unroll
            for(int j = 0; j < 4; j++) bv[j] = sBp[tx*4+j][kk];
            #pragma unroll
            for(int i = 0; i < 4; i++)
                #pragma unroll
                for(int j = 0; j < 4; j++) acc[i][j] += av[i]*bv[j];
        }
        __syncthreads();
    }
    #pragma unroll
    for(int i = 0; i < 4; i++){
        int m = m0 + ty*4 + i; if(m >= M) continue;
        #pragma unroll
        for(int j = 0; j < 4; j++){
            int n = n0 + tx*4 + j; if(n >= N) continue;
            float bb = bias ? bias[n] : 0.f;
            C[(size_t)m*ldc + n] = acc[i][j] + bb;
        }
    }
}

// ---------------- bn6 + lrelu + max over k ----------------
__global__ void k_maxpool(const float* __restrict__ g6, const float* __restrict__ b6,
                          const float* __restrict__ m6, const float* __restrict__ v6,
                          float* __restrict__ f){
    int o = blockIdx.y;
    int c = blockIdx.x*256 + threadIdx.x;
    float s = g6[o]*rsqrtf(v6[o] + 1e-5f);
    float t = b6[o] - m6[o]*s;
    const float* row = g_o2 + (size_t)o*NKCOL + c;
    float mx = -INFINITY;
    #pragma unroll 8
    for(int k = 0; k < KNN; k++){
        float h = s*row[(size_t)k*C5] + t;
        h = lrelu(h);
        mx = fmaxf(mx, h);
    }
    f[(size_t)c*C6 + o] = mx;
}

// ---------------- row softmax ----------------
__global__ __launch_bounds__(256) void k_softmax(){
    int r = blockIdx.x;
    float* p = g_sc + (size_t)r*C5;
    __shared__ float red[256];
    int t = threadIdx.x;
    float v0 = p[t]*SOFT_SCALE, v1 = p[t+256]*SOFT_SCALE;
    red[t] = fmaxf(v0, v1); __syncthreads();
    for(int s = 128; s > 0; s >>= 1){ if(t < s) red[t] = fmaxf(red[t], red[t+s]); __syncthreads(); }
    float mm = red[0]; __syncthreads();
    float e0 = __expf(v0 - mm), e1 = __expf(v1 - mm);
    red[t] = e0 + e1; __syncthreads();
    for(int s = 128; s > 0; s >>= 1){ if(t < s) red[t] += red[t+s]; __syncthreads(); }
    float inv = 1.f/red[0];
    p[t] = e0*inv; p[t+256] = e1*inv;
}

// =============================== host launcher ===============================
extern "C" void kernel_launch(void* const* d_in, const int* in_sizes, int n_in,
                              void* d_out, int out_size){
    const float* x    = (const float*)d_in[0];
    const float* y    = (const float*)d_in[1];
    const float* w5   = (const float*)d_in[2];
    const float* g5   = (const float*)d_in[3];
    const float* b5   = (const float*)d_in[4];
    const float* m5   = (const float*)d_in[5];
    const float* v5   = (const float*)d_in[6];
    const float* w6   = (const float*)d_in[7];
    const float* g6   = (const float*)d_in[8];
    const float* b6   = (const float*)d_in[9];
    const float* m6   = (const float*)d_in[10];
    const float* v6   = (const float*)d_in[11];
    const float* Wq   = (const float*)d_in[12];
    const float* Wk   = (const float*)d_in[13];
    const float* Wv   = (const float*)d_in[14];
    const float* Wout = (const float*)d_in[15];
    const float* bout = (const float*)d_in[16];
    float* out = (float*)d_out;

    float *pxf, *pyf, *pq, *pk, *pv, *psc, *pm;
    cudaGetSymbolAddress((void**)&pxf, g_xf);
    cudaGetSymbolAddress((void**)&pyf, g_yf);
    cudaGetSymbolAddress((void**)&pq,  g_q);
    cudaGetSymbolAddress((void**)&pk,  g_k);
    cudaGetSymbolAddress((void**)&pv,  g_v);
    cudaGetSymbolAddress((void**)&psc, g_sc);
    cudaGetSymbolAddress((void**)&pm,  g_mg);

    cudaFuncSetAttribute(gemm_mma, cudaFuncAttributeMaxDynamicSharedMemorySize, GM_SMEM);

    dim3 t2(16, 16);

    k_w6split<<<(C6*N_PTS + 255)/256, 256>>>(w6);

    for(int br = 0; br < 2; br++){
        const float* p = br ? y : x;
        float* f = br ? pyf : pxf;

        k_xx<<<8, 256>>>(p);
        k_dist<<<dim3(32, 32), t2>>>(p);
        k_topk<<<N_PTS, 256>>>();
        k_ac<<<dim3(8, 32), t2>>>(p, w5, g5, b5, m5, v5);
        k_buildLt<<<dim3(KNN, 64), 256>>>();
        gemm_mma<<<dim3(5, 160), 256, GM_SMEM>>>();
        k_maxpool<<<dim3(2, C6), 256>>>(g6, b6, m6, v6, f);
    }

    // q/k/v
    gemm_nt<<<dim3(8, 8, 1), t2>>>(pxf, Wq, pq, C5, HD, INDIM, INDIM, INDIM, HD, 0, 0, 0, nullptr);
    gemm_nt<<<dim3(8, 8, 1), t2>>>(pyf, Wk, pk, C5, HD, INDIM, INDIM, INDIM, HD, 0, 0, 0, nullptr);
    gemm_nt<<<dim3(8, 8, 1), t2>>>(pyf, Wv, pv, C5, HD, INDIM, INDIM, INDIM, HD, 0, 0, 0, nullptr);

    // scores
    gemm_nt<<<dim3(8, 8, NH), t2>>>(pq, pk, psc, C5, C5, AD, HD, HD, C5,
                                    AD, AD, (long long)C5*C5, nullptr);
    k_softmax<<<NH*C5, 256>>>();

    // weighted
    gemm_nn<<<dim3(1, 8, NH), t2>>>(psc, pv, pm, C5, AD, C5, C5, HD, HD,
                                    (long long)C5*C5, AD, AD);

    // output projection
    gemm_nt<<<dim3((C6+63)/64, 8, 1), t2>>>(pm, Wout, out, C5, C6, HD, HD, HD, C6,
                                            0, 0, 0, bout);
}

// round 9
// speedup vs baseline: 2.2000x; 1.0331x over previous
#include <cuda_runtime.h>
#include <cuda_bf16.h>
#include <math.h>
#include <stdint.h>

#define N_PTS 2048
#define C_IN  512
#define KNN   40
#define C5    512
#define C6    515
#define INDIM C6
#define NKCOL (KNN*C5)         // 20480
#define HD    512
#define NH    8
#define AD    64
#define M_PAD 640              // 5*128, zero-padded rows for w6
#define SOFT_SCALE 0.04419417382415922f

// ---------------- scratch (device globals, no runtime alloc) ----------------
__device__ float g_dist[(size_t)N_PTS*N_PTS];        // 16 MB
__device__ int   g_idx[N_PTS*KNN];
__device__ float g_xx[N_PTS];
__device__ float g_At[(size_t)N_PTS*C5];             // [n][o]  raw s5*wa @ x
__device__ float g_Ct[(size_t)N_PTS*C5];             // [n][o]  raw s5*wd @ x
__device__ float g_tt[C5];                           // bn5 bias term
__device__ __nv_bfloat16 g_xhi[(size_t)N_PTS*C_IN];  // x transposed [n][c]
__device__ __nv_bfloat16 g_xlo[(size_t)N_PTS*C_IN];
__device__ __nv_bfloat16 g_w5ahi[C5*C_IN];           // s5*w5a   [o][c]
__device__ __nv_bfloat16 g_w5alo[C5*C_IN];
__device__ __nv_bfloat16 g_w5dhi[C5*C_IN];           // s5*(w5b-w5a)
__device__ __nv_bfloat16 g_w5dlo[C5*C_IN];
__device__ __nv_bfloat16 g_w6hi[(size_t)M_PAD*N_PTS];
__device__ __nv_bfloat16 g_w6lo[(size_t)M_PAD*N_PTS];
__device__ __nv_bfloat16 g_Lthi[(size_t)NKCOL*N_PTS];
__device__ __nv_bfloat16 g_Ltlo[(size_t)NKCOL*N_PTS];
__device__ float g_o2[(size_t)C6*NKCOL];
__device__ float g_xf[C5*C6];
__device__ float g_yf[C5*C6];
__device__ float g_q [C5*HD];
__device__ float g_k [C5*HD];
__device__ float g_v [C5*HD];
__device__ float g_sc[(size_t)NH*C5*C5];
__device__ float g_mg[C5*HD];

__device__ __forceinline__ float lrelu(float v){ return v > 0.f ? v : 0.2f*v; }

// ====================== PTX helpers (all baseline sm_80+ features) ======================
__device__ __forceinline__ uint32_t smem_u32(const void* p){
    uint32_t a;
    asm("{ .reg .u64 t; cvta.to.shared.u64 t, %1; cvt.u32.u64 %0, t; }" : "=r"(a) : "l"(p));
    return a;
}
__device__ __forceinline__ void cpa16(uint32_t dst, const void* src){
    asm volatile("cp.async.cg.shared.global [%0], [%1], 16;" :: "r"(dst), "l"(src));
}
#define CPA_COMMIT() asm volatile("cp.async.commit_group;" ::: "memory")
#define CPA_WAIT1()  asm volatile("cp.async.wait_group 1;" ::: "memory")
#define CPA_WAIT0()  asm volatile("cp.async.wait_group 0;" ::: "memory")

#define LDM4(r, ad) \
    asm volatile("ldmatrix.sync.aligned.m8n8.x4.shared.b16 {%0,%1,%2,%3}, [%4];" \
        : "=r"((r)[0]), "=r"((r)[1]), "=r"((r)[2]), "=r"((r)[3]) : "r"(ad))

#define MMA_BF16(d, a, b) \
    asm volatile("mma.sync.aligned.m16n8k16.row.col.f32.bf16.bf16.f32 " \
        "{%0,%1,%2,%3},{%4,%5,%6,%7},{%8,%9},{%0,%1,%2,%3};" \
        : "+f"((d)[0]), "+f"((d)[1]), "+f"((d)[2]), "+f"((d)[3]) \
        : "r"((a)[0]), "r"((a)[1]), "r"((a)[2]), "r"((a)[3]), "r"((b)[0]), "r"((b)[1]))

// ---------------- xx[n] = sum_c x[c,n]^2 ----------------
__global__ void k_xx(const float* __restrict__ x){
    int n = blockIdx.x*blockDim.x + threadIdx.x;
    if(n < N_PTS){
        float s = 0.f;
        for(int c = 0; c < C_IN; c++){ float v = x[(size_t)c*N_PTS + n]; s += v*v; }
        g_xx[n] = s;
    }
}

// ---------------- neg sq dist, symmetric: only blocks m0<=n0, mirror-write ----------------
__global__ __launch_bounds__(256) void k_dist(const float* __restrict__ x){
    if(blockIdx.x > blockIdx.y) return;    // keep m-block <= n-block
    __shared__ __align__(16) float sN[16][64];
    __shared__ __align__(16) float sM[16][64];
    int tx = threadIdx.x, ty = threadIdx.y, t = ty*16 + tx;
    int n0 = blockIdx.y*64, m0 = blockIdx.x*64;
    float acc[4][4] = {};
    for(int c0 = 0; c0 < C_IN; c0 += 16){
        #pragma unroll
        for(int i = 0; i < 4; i++){
            int e = t + i*256; int kt = e >> 6; int col = e & 63;
            sN[kt][col] = x[(size_t)(c0+kt)*N_PTS + n0 + col];
            sM[kt][col] = x[(size_t)(c0+kt)*N_PTS + m0 + col];
        }
        __syncthreads();
        #pragma unroll
        for(int kk = 0; kk < 16; kk++){
            float4 a4 = *(const float4*)&sN[kk][ty*4];
            float4 b4 = *(const float4*)&sM[kk][tx*4];
            float av[4] = {a4.x,a4.y,a4.z,a4.w};
            float bv[4] = {b4.x,b4.y,b4.z,b4.w};
            #pragma unroll
            for(int i = 0; i < 4; i++)
                #pragma unroll
                for(int j = 0; j < 4; j++) acc[i][j] += av[i]*bv[j];
        }
        __syncthreads();
    }
    float xnv[4], xmv[4], v[4][4];
    #pragma unroll
    for(int i = 0; i < 4; i++) xnv[i] = g_xx[n0 + ty*4 + i];
    #pragma unroll
    for(int j = 0; j < 4; j++) xmv[j] = g_xx[m0 + tx*4 + j];
    #pragma unroll
    for(int i = 0; i < 4; i++)
        #pragma unroll
        for(int j = 0; j < 4; j++) v[i][j] = 2.f*acc[i][j] - xnv[i] - xmv[j];
    #pragma unroll
    for(int i = 0; i < 4; i++){
        float4 w = make_float4(v[i][0], v[i][1], v[i][2], v[i][3]);
        *(float4*)&g_dist[(size_t)(n0 + ty*4 + i)*N_PTS + m0 + tx*4] = w;
    }
    if(blockIdx.x != blockIdx.y){
        #pragma unroll
        for(int j = 0; j < 4; j++){
            float4 w = make_float4(v[0][j], v[1][j], v[2][j], v[3][j]);
            *(float4*)&g_dist[(size_t)(m0 + tx*4 + j)*N_PTS + n0 + ty*4] = w;
        }
    }
}

// ---------------- top-40 per row: 4-pass radix select + exact jax ordering ----------------
__global__ __launch_bounds__(256) void k_topk(){
    __shared__ int hist[256];
    __shared__ int s_nextb, s_nextneed;
    __shared__ int s_cnt, s_eqcnt;
    __shared__ uint32_t s_selu[KNN];
    __shared__ int      s_seli[KNN];
    __shared__ int      s_eq[64];

    int n = blockIdx.x;
    int t = threadIdx.x;
    const float* row = g_dist + (size_t)n*N_PTS;

    uint32_t u[8];
    #pragma unroll
    for(int i = 0; i < 8; i++){
        uint32_t b = __float_as_uint(row[t + 256*i]);
        u[i] = (b & 0x80000000u) ? ~b : (b | 0x80000000u);
    }

    uint32_t prefix = 0, mask = 0;
    int need = KNN;
    #pragma unroll
    for(int pass = 0; pass < 4; pass++){
        int shift = 24 - pass*8;
        hist[t] = 0;
        __syncthreads();
        #pragma unroll
        for(int i = 0; i < 8; i++)
            if((u[i] & mask) == prefix) atomicAdd(&hist[(u[i] >> shift) & 0xFF], 1);
        __syncthreads();
        int v = hist[t];
        for(int off = 1; off < 256; off <<= 1){
            int w = (t + off < 256) ? hist[t + off] : 0;
            __syncthreads();
            v += w; hist[t] = v;
            __syncthreads();
        }
        int Sn = (t < 255) ? hist[t + 1] : 0;
        if(v >= need && Sn < need){ s_nextb = t; s_nextneed = need - Sn; }
        __syncthreads();
        prefix |= ((uint32_t)s_nextb) << shift;
        mask   |= 0xFFu << shift;
        need = s_nextneed;
        __syncthreads();
    }
    if(t == 0){ s_cnt = 0; s_eqcnt = 0; }
    __syncthreads();
    #pragma unroll
    for(int i = 0; i < 8; i++){
        if(u[i] > prefix){
            int p = atomicAdd(&s_cnt, 1);
            s_selu[p] = u[i]; s_seli[p] = t + 256*i;
        } else if(u[i] == prefix){
            int p = atomicAdd(&s_eqcnt, 1);
            if(p < 64) s_eq[p] = t + 256*i;
        }
    }
    __syncthreads();
    if(t == 0){
        int cnt = s_cnt;
        int e = s_eqcnt < 64 ? s_eqcnt : 64;
        for(int j = 0; j < need; j++){
            int best = 0x7FFFFFFF, bi = -1;
            for(int q = 0; q < e; q++)
                if(s_eq[q] < best){ best = s_eq[q]; bi = q; }
            s_selu[cnt + j] = prefix; s_seli[cnt + j] = best;
            s_eq[bi] = 0x7FFFFFFF;
        }
    }
    __syncthreads();
    if(t < KNN){
        uint32_t mu = s_selu[t]; int mi = s_seli[t];
        int rank = 0;
        #pragma unroll
        for(int q = 0; q < KNN; q++){
            uint32_t qu = s_selu[q]; int qi = s_seli[q];
            rank += (qu > mu) || (qu == mu && qi < mi);
        }
        g_idx[n*KNN + rank] = mi;
    }
}

// ---------------- w5 split (once): fold bn5 scale; also tt ----------------
__global__ void k_w5split(const float* __restrict__ w5, const float* __restrict__ g5,
                          const float* __restrict__ b5, const float* __restrict__ m5,
                          const float* __restrict__ v5){
    int i = blockIdx.x*256 + threadIdx.x;
    if(i >= C5*C_IN) return;
    int o = i >> 9, c = i & 511;
    float s = g5[o]*rsqrtf(v5[o] + 1e-5f);
    float wa = s*w5[(size_t)o*1024 + c];
    float wd = s*(w5[(size_t)o*1024 + 512 + c] - w5[(size_t)o*1024 + c]);
    __nv_bfloat16 h;
    h = __float2bfloat16(wa); g_w5ahi[i] = h; g_w5alo[i] = __float2bfloat16(wa - __bfloat162float(h));
    h = __float2bfloat16(wd); g_w5dhi[i] = h; g_w5dlo[i] = __float2bfloat16(wd - __bfloat162float(h));
    if(c == 0) g_tt[o] = b5[o] - m5[o]*s;
}

// ---------------- x transpose+split: [c][n] fp32 -> [n][c] bf16 hi/lo ----------------
__global__ __launch_bounds__(256) void k_xsplit(const float* __restrict__ x){
    __shared__ float tile[32][33];
    int n0 = blockIdx.x*32, c0 = blockIdx.y*32;
    int tid = threadIdx.x;
    int a = tid >> 5, b = tid & 31;       // a=0..7, b=0..31
    #pragma unroll
    for(int p = 0; p < 4; p++){
        int cl = p*8 + a;
        tile[cl][b] = x[(size_t)(c0+cl)*N_PTS + n0 + b];
    }
    __syncthreads();
    #pragma unroll
    for(int p = 0; p < 4; p++){
        int nl = p*8 + a;
        float v = tile[b][nl];
        __nv_bfloat16 h = __float2bfloat16(v);
        size_t o = (size_t)(n0+nl)*C_IN + c0 + b;
        g_xhi[o] = h;
        g_xlo[o] = __float2bfloat16(v - __bfloat162float(h));
    }
}

// ---------------- w6 split to bf16 hi/lo ----------------
__global__ void k_w6split(const float* __restrict__ w6){
    int i = blockIdx.x*256 + threadIdx.x;
    if(i < C6*N_PTS){
        float v = w6[i];
        __nv_bfloat16 h = __float2bfloat16(v);
        float r = v - __bfloat162float(h);
        g_w6hi[i] = h;
        g_w6lo[i] = __float2bfloat16(r);
    }
}

// ---------------- build Lt[col][n] bf16 hi/lo (transposed, split) ----------------
__global__ __launch_bounds__(256) void k_buildLt(){
    __shared__ uint32_t sbuf[32][257];
    int k  = blockIdx.x;
    int n0 = blockIdx.y*32;
    int tid = threadIdx.x, wid = tid>>5, lane = tid&31;
    for(int half = 0; half < 2; half++){
        int c0 = half*256;
        #pragma unroll
        for(int q = 0; q < 4; q++){
            int nloc = wid*4 + q;
            int n = n0 + nloc;
            int j = g_idx[n*KNN + k];
            for(int c = lane; c < 256; c += 32){
                float v = g_At[(size_t)j*C5 + c0 + c] + g_Ct[(size_t)n*C5 + c0 + c] + g_tt[c0 + c];
                v = lrelu(v);
                __nv_bfloat16 h = __float2bfloat16(v);
                float r = v - __bfloat162float(h);
                __nv_bfloat16 l = __float2bfloat16(r);
                sbuf[nloc][c] = (uint32_t)__bfloat16_as_ushort(h) | ((uint32_t)__bfloat16_as_ushort(l) << 16);
            }
        }
        __syncthreads();
        for(int c = wid; c < 256; c += 8){
            uint32_t u = sbuf[lane][c];
            size_t row = (size_t)(k*C5 + c0 + c);
            g_Lthi[row*N_PTS + n0 + lane] = __ushort_as_bfloat16((unsigned short)(u & 0xFFFFu));
            g_Ltlo[row*N_PTS + n0 + lane] = __ushort_as_bfloat16((unsigned short)(u >> 16));
        }
        __syncthreads();
    }
}

// ============ unified warp-MMA bf16 split GEMM: C[m][n] = sum_k A[m,k]*B[n,k] ============
#define GM_PITCHB 80
#define GM_AOFF   0
#define GM_BOFF   20480
#define GM_STG    40960
#define GM_SMEM   (2*GM_STG)

__device__ __forceinline__ void gm_load_chunk(uint32_t sb, int s,
        const __nv_bfloat16* Ahi, const __nv_bfloat16* Alo,
        const __nv_bfloat16* Bhi, const __nv_bfloat16* Blo,
        int lda, int ldb, int m0, int n0, int ck, int tid){
    uint32_t base = sb + s*GM_STG;
    #pragma unroll
    for(int p = 0; p < 4; p++){
        int u = p*256 + tid;
        int hl = u >> 9, rem = u & 511, row = rem >> 2, seg = rem & 3;
        const __nv_bfloat16* src = (hl ? Alo : Ahi) + (size_t)(m0+row)*lda + ck*32 + seg*8;
        cpa16(base + GM_AOFF + hl*10240 + row*GM_PITCHB + seg*16, src);
    }
    #pragma unroll
    for(int p = 0; p < 4; p++){
        int u = p*256 + tid;
        int hl = u >> 9, rem = u & 511, row = rem >> 2, seg = rem & 3;
        const __nv_bfloat16* src = (hl ? Blo : Bhi) + (size_t)(n0+row)*ldb + ck*32 + seg*8;
        cpa16(base + GM_BOFF + hl*10240 + row*GM_PITCHB + seg*16, src);
    }
}

__global__ void __launch_bounds__(256, 1) gemm_bf16split(
        const __nv_bfloat16* __restrict__ Ahi, const __nv_bfloat16* __restrict__ Alo,
        const __nv_bfloat16* __restrict__ Bhi, const __nv_bfloat16* __restrict__ Blo,
        float* __restrict__ C, int nch, int lda, int ldb, size_t ldc, int Mlim){
    extern __shared__ __align__(128) char smem[];
    uint32_t sb = smem_u32(smem);
    int tid = threadIdx.x, lane = tid & 31, wid = tid >> 5;
    int wm = wid & 3, wn = wid >> 2;
    int m0 = blockIdx.x*128, n0 = blockIdx.y*128;

    float acc[2][8][4];
    #pragma unroll
    for(int i = 0; i < 2; i++)
        #pragma unroll
        for(int j = 0; j < 8; j++)
            #pragma unroll
            for(int q = 0; q < 4; q++) acc[i][j][q] = 0.f;

    gm_load_chunk(sb, 0, Ahi, Alo, Bhi, Blo, lda, ldb, m0, n0, 0, tid);
    CPA_COMMIT();

    int a_row = wm*32 + (lane & 15);
    int a_col2 = ((lane >> 4) * 8) * 2;
    int b_row = wn*64 + (lane & 7) + ((lane >> 4) << 3);
    int b_col2 = (((lane >> 3) & 1) * 8) * 2;

    for(int c = 0; c < nch; c++){
        if(c + 1 < nch){
            gm_load_chunk(sb, (c+1)&1, Ahi, Alo, Bhi, Blo, lda, ldb, m0, n0, c+1, tid);
            CPA_COMMIT();
            CPA_WAIT1();
        } else {
            CPA_WAIT0();
        }
        __syncthreads();

        uint32_t base = sb + (c&1)*GM_STG;
        #pragma unroll
        for(int h = 0; h < 2; h++){
            int kb2 = h*16*2;
            uint32_t ah[2][4], al[2][4];
            #pragma unroll
            for(int mt = 0; mt < 2; mt++){
                uint32_t ad = base + GM_AOFF + (a_row + mt*16)*GM_PITCHB + a_col2 + kb2;
                LDM4(ah[mt], ad);
                LDM4(al[mt], ad + 10240);
            }
            uint32_t bh[8][2], bl[8][2];
            #pragma unroll
            for(int np = 0; np < 4; np++){
                uint32_t bd = base + GM_BOFF + (b_row + np*16)*GM_PITCHB + b_col2 + kb2;
                uint32_t r[4];
                LDM4(r, bd);
                bh[np*2][0] = r[0]; bh[np*2][1] = r[1]; bh[np*2+1][0] = r[2]; bh[np*2+1][1] = r[3];
                LDM4(r, bd + 10240);
                bl[np*2][0] = r[0]; bl[np*2][1] = r[1]; bl[np*2+1][0] = r[2]; bl[np*2+1][1] = r[3];
            }
            #pragma unroll
            for(int mt = 0; mt < 2; mt++)
                #pragma unroll
                for(int nt = 0; nt < 8; nt++){
                    MMA_BF16(acc[mt][nt], ah[mt], bh[nt]);
                    MMA_BF16(acc[mt][nt], ah[mt], bl[nt]);
                    MMA_BF16(acc[mt][nt], al[mt], bh[nt]);
                }
        }
        __syncthreads();
    }

    int g = lane >> 2, tg = lane & 3;
    #pragma unroll
    for(int mt = 0; mt < 2; mt++){
        int m = m0 + wm*32 + mt*16 + g;
        #pragma unroll
        for(int nt = 0; nt < 8; nt++){
            int col = n0 + wn*64 + nt*8 + tg*2;
            if(m < Mlim)
                *(float2*)(C + (size_t)m*ldc + col) = make_float2(acc[mt][nt][0], acc[mt][nt][1]);
            if(m + 8 < Mlim)
                *(float2*)(C + (size_t)(m+8)*ldc + col) = make_float2(acc[mt][nt][2], acc[mt][nt][3]);
        }
    }
}

// ---------------- generic gemm_nn (attention tail) ----------------
__global__ __launch_bounds__(256) void gemm_nn(const float* __restrict__ A, const float* __restrict__ B,
                       float* __restrict__ C, int M, int N, int K,
                       int lda, int ldb, int ldc,
                       long long sA, long long sB, long long sC){
    A += (size_t)blockIdx.z * sA; B += (size_t)blockIdx.z * sB; C += (size_t)blockIdx.z * sC;
    __shared__ float sAp[64][17];
    __shared__ __align__(16) float sBt[16][64];
    int tx = threadIdx.x, ty = threadIdx.y, t = ty*16 + tx;
    int m0 = blockIdx.y*64, n0 = blockIdx.x*64;
    float acc[4][4] = {};
    for(int k0 = 0; k0 < K; k0 += 16){
        #pragma unroll
        for(int i = 0; i < 4; i++){
            int e = t + i*256; int kt = e & 15; int mi = e >> 4;
            int m = m0 + mi, k = k0 + kt;
            sAp[mi][kt] = (m < M && k < K) ? A[(size_t)m*lda + k] : 0.f;
        }
        #pragma unroll
        for(int i = 0; i < 4; i++){
            int e = t + i*256; int ni = e & 63; int kt = e >> 6;
            int k = k0 + kt, n = n0 + ni;
            sBt[kt][ni] = (k < K && n < N) ? B[(size_t)k*ldb + n] : 0.f;
        }
        __syncthreads();
        #pragma unroll
        for(int kk = 0; kk < 16; kk++){
            float av[4];
            #pragma unroll
            for(int i = 0; i < 4; i++) av[i] = sAp[ty*4+i][kk];
            float4 b4 = *(const float4*)&sBt[kk][tx*4];
            float bv[4] = {b4.x,b4.y,b4.z,b4.w};
            #pragma unroll
            for(int i = 0; i < 4; i++)
                #pragma unroll
                for(int j = 0; j < 4; j++) acc[i][j] += av[i]*bv[j];
        }
        __syncthreads();
    }
    #pragma unroll
    for(int i = 0; i < 4; i++){
        int m = m0 + ty*4 + i; if(m >= M) continue;
        #pragma unroll
        for(int j = 0; j < 4; j++){
            int n = n0 + tx*4 + j; if(n >= N) continue;
            C[(size_t)m*ldc + n] = acc[i][j];
        }
    }
}

// ---------------- generic gemm_nt (+bias) ----------------
__global__ __launch_bounds__(256) void gemm_nt(const float* __restrict__ A, const float* __restrict__ B,
                       float* __restrict__ C, int M, int N, int K,
                       int lda, int ldb, int ldc,
                       long long sA, long long sB, long long sC,
                       const float* __restrict__ bias){
    A += (size_t)blockIdx.z * sA; B += (size_t)blockIdx.z * sB; C += (size_t)blockIdx.z * sC;
    __shared__ float sAp[64][17];
    __shared__ float sBp[64][17];
    int tx = threadIdx.x, ty = threadIdx.y, t = ty*16 + tx;
    int m0 = blockIdx.y*64, n0 = blockIdx.x*64;
    float acc[4][4] = {};
    for(int k0 = 0; k0 < K; k0 += 16){
        #pragma unroll
        for(int i = 0; i < 4; i++){
            int e = t + i*256; int kt = e & 15; int mi = e >> 4;
            int m = m0 + mi, k = k0 + kt;
            sAp[mi][kt] = (m < M && k < K) ? A[(size_t)m*lda + k] : 0.f;
        }
        #pragma unroll
        for(int i = 0; i < 4; i++){
            int e = t + i*256; int kt = e & 15; int ni = e >> 4;
            int n = n0 + ni, k = k0 + kt;
            sBp[ni][kt] = (n < N && k < K) ? B[(size_t)n*ldb + k] : 0.f;
        }
        __syncthreads();
        #pragma unroll
        for(int kk = 0; kk < 16; kk++){
            float av[4], bv[4];
            #pragma unroll
            for(int i = 0; i < 4; i++) av[i] = sAp[ty*4+i][kk];
            #pragma unroll
            for(int j = 0; j < 4; j++) bv[j] = sBp[tx*4+j][kk];
            #pragma unroll
            for(int i = 0; i < 4; i++)
                #pragma unroll
                for(int j = 0; j < 4; j++) acc[i][j] += av[i]*bv[j];
        }
        __syncthreads();
    }
    #pragma unroll
    for(int i = 0; i < 4; i++){
        int m = m0 + ty*4 + i; if(m >= M) continue;
        #pragma unroll
        for(int j = 0; j < 4; j++){
            int n = n0 + tx*4 + j; if(n >= N) continue;
            float bb = bias ? bias[n] : 0.f;
            C[(size_t)m*ldc + n] = acc[i][j] + bb;
        }
    }
}

// ---------------- bn6 + lrelu + max over k ----------------
__global__ void k_maxpool(const float* __restrict__ g6, const float* __restrict__ b6,
                          const float* __restrict__ m6, const float* __restrict__ v6,
                          float* __restrict__ f){
    int o = blockIdx.y;
    int c = blockIdx.x*256 + threadIdx.x;
    float s = g6[o]*rsqrtf(v6[o] + 1e-5f);
    float t = b6[o] - m6[o]*s;
    const float* row = g_o2 + (size_t)o*NKCOL + c;
    float mx = -INFINITY;
    #pragma unroll 8
    for(int k = 0; k < KNN; k++){
        float h = s*row[(size_t)k*C5] + t;
        h = lrelu(h);
        mx = fmaxf(mx, h);
    }
    f[(size_t)c*C6 + o] = mx;
}

// ---------------- row softmax ----------------
__global__ __launch_bounds__(256) void k_softmax(){
    int r = blockIdx.x;
    float* p = g_sc + (size_t)r*C5;
    __shared__ float red[256];
    int t = threadIdx.x;
    float v0 = p[t]*SOFT_SCALE, v1 = p[t+256]*SOFT_SCALE;
    red[t] = fmaxf(v0, v1); __syncthreads();
    for(int s = 128; s > 0; s >>= 1){ if(t < s) red[t] = fmaxf(red[t], red[t+s]); __syncthreads(); }
    float mm = red[0]; __syncthreads();
    float e0 = __expf(v0 - mm), e1 = __expf(v1 - mm);
    red[t] = e0 + e1; __syncthreads();
    for(int s = 128; s > 0; s >>= 1){ if(t < s) red[t] += red[t+s]; __syncthreads(); }
    float inv = 1.f/red[0];
    p[t] = e0*inv; p[t+256] = e1*inv;
}

// =============================== host launcher ===============================
extern "C" void kernel_launch(void* const* d_in, const int* in_sizes, int n_in,
                              void* d_out, int out_size){
    const float* x    = (const float*)d_in[0];
    const float* y    = (const float*)d_in[1];
    const float* w5   = (const float*)d_in[2];
    const float* g5   = (const float*)d_in[3];
    const float* b5   = (const float*)d_in[4];
    const float* m5   = (const float*)d_in[5];
    const float* v5   = (const float*)d_in[6];
    const float* w6   = (const float*)d_in[7];
    const float* g6   = (const float*)d_in[8];
    const float* b6   = (const float*)d_in[9];
    const float* m6   = (const float*)d_in[10];
    const float* v6   = (const float*)d_in[11];
    const float* Wq   = (const float*)d_in[12];
    const float* Wk   = (const float*)d_in[13];
    const float* Wv   = (const float*)d_in[14];
    const float* Wout = (const float*)d_in[15];
    const float* bout = (const float*)d_in[16];
    float* out = (float*)d_out;

    float *pxf, *pyf, *pq, *pk, *pv, *psc, *pm, *pAt, *pCt, *pO2;
    __nv_bfloat16 *pxhi, *pxlo, *pw5ahi, *pw5alo, *pw5dhi, *pw5dlo, *pw6hi, *pw6lo, *pLthi, *pLtlo;
    cudaGetSymbolAddress((void**)&pxf, g_xf);
    cudaGetSymbolAddress((void**)&pyf, g_yf);
    cudaGetSymbolAddress((void**)&pq,  g_q);
    cudaGetSymbolAddress((void**)&pk,  g_k);
    cudaGetSymbolAddress((void**)&pv,  g_v);
    cudaGetSymbolAddress((void**)&psc, g_sc);
    cudaGetSymbolAddress((void**)&pm,  g_mg);
    cudaGetSymbolAddress((void**)&pAt, g_At);
    cudaGetSymbolAddress((void**)&pCt, g_Ct);
    cudaGetSymbolAddress((void**)&pO2, g_o2);
    cudaGetSymbolAddress((void**)&pxhi, g_xhi);
    cudaGetSymbolAddress((void**)&pxlo, g_xlo);
    cudaGetSymbolAddress((void**)&pw5ahi, g_w5ahi);
    cudaGetSymbolAddress((void**)&pw5alo, g_w5alo);
    cudaGetSymbolAddress((void**)&pw5dhi, g_w5dhi);
    cudaGetSymbolAddress((void**)&pw5dlo, g_w5dlo);
    cudaGetSymbolAddress((void**)&pw6hi, g_w6hi);
    cudaGetSymbolAddress((void**)&pw6lo, g_w6lo);
    cudaGetSymbolAddress((void**)&pLthi, g_Lthi);
    cudaGetSymbolAddress((void**)&pLtlo, g_Ltlo);

    cudaFuncSetAttribute(gemm_bf16split, cudaFuncAttributeMaxDynamicSharedMemorySize, GM_SMEM);

    dim3 t2(16, 16);

    k_w6split<<<(C6*N_PTS + 255)/256, 256>>>(w6);
    k_w5split<<<(C5*C_IN + 255)/256, 256>>>(w5, g5, b5, m5, v5);

    for(int br = 0; br < 2; br++){
        const float* p = br ? y : x;
        float* f = br ? pyf : pxf;

        k_xx<<<8, 256>>>(p);
        k_dist<<<dim3(32, 32), t2>>>(p);
        k_topk<<<N_PTS, 256>>>();
        k_xsplit<<<dim3(64, 16), 256>>>(p);
        // At[n][o] = (s5*w5a) @ x ; Ct[n][o] = (s5*(w5b-w5a)) @ x
        gemm_bf16split<<<dim3(16, 4), 256, GM_SMEM>>>(pxhi, pxlo, pw5ahi, pw5alo,
                pAt, C_IN/32, C_IN, C_IN, (size_t)C5, N_PTS);
        gemm_bf16split<<<dim3(16, 4), 256, GM_SMEM>>>(pxhi, pxlo, pw5dhi, pw5dlo,
                pCt, C_IN/32, C_IN, C_IN, (size_t)C5, N_PTS);
        k_buildLt<<<dim3(KNN, 64), 256>>>();
        // out2 = w6 @ L
        gemm_bf16split<<<dim3(5, 160), 256, GM_SMEM>>>(pw6hi, pw6lo, pLthi, pLtlo,
                pO2, N_PTS/32, N_PTS, N_PTS, (size_t)NKCOL, C6);
        k_maxpool<<<dim3(2, C6), 256>>>(g6, b6, m6, v6, f);
    }

    // q/k/v
    gemm_nt<<<dim3(8, 8, 1), t2>>>(pxf, Wq, pq, C5, HD, INDIM, INDIM, INDIM, HD, 0, 0, 0, nullptr);
    gemm_nt<<<dim3(8, 8, 1), t2>>>(pyf, Wk, pk, C5, HD, INDIM, INDIM, INDIM, HD, 0, 0, 0, nullptr);
    gemm_nt<<<dim3(8, 8, 1), t2>>>(pyf, Wv, pv, C5, HD, INDIM, INDIM, INDIM, HD, 0, 0, 0, nullptr);

    // scores
    gemm_nt<<<dim3(8, 8, NH), t2>>>(pq, pk, psc, C5, C5, AD, HD, HD, C5,
                                    AD, AD, (long long)C5*C5, nullptr);
    k_softmax<<<NH*C5, 256>>>();

    // weighted
    gemm_nn<<<dim3(1, 8, NH), t2>>>(psc, pv, pm, C5, AD, C5, C5, HD, HD,
                                    (long long)C5*C5, AD, AD);

    // output projection
    gemm_nt<<<dim3((C6+63)/64, 8, 1), t2>>>(pm, Wout, out, C5, C6, HD, HD, HD, C6,
                                            0, 0, 0, bout);
}

// round 10
// speedup vs baseline: 2.2907x; 1.0412x over previous
#include <cuda_runtime.h>
#include <cuda_fp16.h>
#include <math.h>
#include <stdint.h>

#define N_PTS 2048
#define C_IN  512
#define KNN   40
#define C5    512
#define C6    515
#define INDIM C6
#define NKCOL (KNN*C5)         // 20480
#define HD    512
#define NH    8
#define AD    64
#define M_PAD 640              // 5*128, zero-padded rows for w6
#define SOFT_SCALE 0.04419417382415922f

// ---------------- scratch (device globals, no runtime alloc) ----------------
__device__ float g_dist[(size_t)N_PTS*N_PTS];        // 16 MB
__device__ int   g_idx[N_PTS*KNN];
__device__ float g_xx[N_PTS];
__device__ float g_At[(size_t)N_PTS*C5];             // [n][o]
__device__ float g_Ct[(size_t)N_PTS*C5];             // [n][o]
__device__ float g_tt[C5];                           // bn5 bias term
__device__ __half g_xhi[(size_t)N_PTS*C_IN];         // x transposed [n][c] fp16 hi/lo
__device__ __half g_xlo[(size_t)N_PTS*C_IN];
__device__ __half g_w5ahi[C5*C_IN];                  // s5*w5a [o][c]
__device__ __half g_w5alo[C5*C_IN];
__device__ __half g_w5dhi[C5*C_IN];                  // s5*(w5b-w5a)
__device__ __half g_w5dlo[C5*C_IN];
__device__ __half g_w6h[(size_t)M_PAD*N_PTS];        // w6 single fp16 [o][n]
__device__ __half g_Lthi[(size_t)NKCOL*N_PTS];       // L fp16 hi/lo [col][n]
__device__ __half g_Ltlo[(size_t)NKCOL*N_PTS];
__device__ float g_o2[(size_t)C6*NKCOL];
__device__ float g_xf[C5*C6];
__device__ float g_yf[C5*C6];
__device__ float g_q [C5*HD];
__device__ float g_k [C5*HD];
__device__ float g_v [C5*HD];
__device__ float g_sc[(size_t)NH*C5*C5];
__device__ float g_mg[C5*HD];

__device__ __forceinline__ float lrelu(float v){ return v > 0.f ? v : 0.2f*v; }

// ====================== PTX helpers (all baseline sm_80+ features) ======================
__device__ __forceinline__ uint32_t smem_u32(const void* p){
    uint32_t a;
    asm("{ .reg .u64 t; cvta.to.shared.u64 t, %1; cvt.u32.u64 %0, t; }" : "=r"(a) : "l"(p));
    return a;
}
__device__ __forceinline__ void cpa16(uint32_t dst, const void* src){
    asm volatile("cp.async.cg.shared.global [%0], [%1], 16;" :: "r"(dst), "l"(src));
}
#define CPA_COMMIT() asm volatile("cp.async.commit_group;" ::: "memory")
#define CPA_WAIT1()  asm volatile("cp.async.wait_group 1;" ::: "memory")
#define CPA_WAIT0()  asm volatile("cp.async.wait_group 0;" ::: "memory")

#define LDM4(r, ad) \
    asm volatile("ldmatrix.sync.aligned.m8n8.x4.shared.b16 {%0,%1,%2,%3}, [%4];" \
        : "=r"((r)[0]), "=r"((r)[1]), "=r"((r)[2]), "=r"((r)[3]) : "r"(ad))

#define MMA_F16(d, a, b) \
    asm volatile("mma.sync.aligned.m16n8k16.row.col.f32.f16.f16.f32 " \
        "{%0,%1,%2,%3},{%4,%5,%6,%7},{%8,%9},{%0,%1,%2,%3};" \
        : "+f"((d)[0]), "+f"((d)[1]), "+f"((d)[2]), "+f"((d)[3]) \
        : "r"((a)[0]), "r"((a)[1]), "r"((a)[2]), "r"((a)[3]), "r"((b)[0]), "r"((b)[1]))

// ---------------- xx[n] = sum_c x[c,n]^2 ----------------
__global__ void k_xx(const float* __restrict__ x){
    int n = blockIdx.x*blockDim.x + threadIdx.x;
    if(n < N_PTS){
        float s = 0.f;
        for(int c = 0; c < C_IN; c++){ float v = x[(size_t)c*N_PTS + n]; s += v*v; }
        g_xx[n] = s;
    }
}

// ---------------- neg sq dist, symmetric, triangular grid (528 blocks) ----------------
__global__ __launch_bounds__(256) void k_dist(const float* __restrict__ x){
    int bi = blockIdx.x;
    int by = (int)((sqrtf(8.f*bi + 1.f) - 1.f)*0.5f);
    while(((by + 1)*(by + 2))/2 <= bi) ++by;
    while((by*(by + 1))/2 > bi) --by;
    int bx = bi - (by*(by + 1))/2;

    __shared__ __align__(16) float sN[16][64];
    __shared__ __align__(16) float sM[16][64];
    int tx = threadIdx.x, ty = threadIdx.y, t = ty*16 + tx;
    int n0 = by*64, m0 = bx*64;
    float acc[4][4] = {};
    for(int c0 = 0; c0 < C_IN; c0 += 16){
        #pragma unroll
        for(int i = 0; i < 4; i++){
            int e = t + i*256; int kt = e >> 6; int col = e & 63;
            sN[kt][col] = x[(size_t)(c0+kt)*N_PTS + n0 + col];
            sM[kt][col] = x[(size_t)(c0+kt)*N_PTS + m0 + col];
        }
        __syncthreads();
        #pragma unroll
        for(int kk = 0; kk < 16; kk++){
            float4 a4 = *(const float4*)&sN[kk][ty*4];
            float4 b4 = *(const float4*)&sM[kk][tx*4];
            float av[4] = {a4.x,a4.y,a4.z,a4.w};
            float bv[4] = {b4.x,b4.y,b4.z,b4.w};
            #pragma unroll
            for(int i = 0; i < 4; i++)
                #pragma unroll
                for(int j = 0; j < 4; j++) acc[i][j] += av[i]*bv[j];
        }
        __syncthreads();
    }
    float xnv[4], xmv[4], v[4][4];
    #pragma unroll
    for(int i = 0; i < 4; i++) xnv[i] = g_xx[n0 + ty*4 + i];
    #pragma unroll
    for(int j = 0; j < 4; j++) xmv[j] = g_xx[m0 + tx*4 + j];
    #pragma unroll
    for(int i = 0; i < 4; i++)
        #pragma unroll
        for(int j = 0; j < 4; j++) v[i][j] = 2.f*acc[i][j] - xnv[i] - xmv[j];
    #pragma unroll
    for(int i = 0; i < 4; i++){
        float4 w = make_float4(v[i][0], v[i][1], v[i][2], v[i][3]);
        *(float4*)&g_dist[(size_t)(n0 + ty*4 + i)*N_PTS + m0 + tx*4] = w;
    }
    if(bx != by){
        #pragma unroll
        for(int j = 0; j < 4; j++){
            float4 w = make_float4(v[0][j], v[1][j], v[2][j], v[3][j]);
            *(float4*)&g_dist[(size_t)(m0 + tx*4 + j)*N_PTS + n0 + ty*4] = w;
        }
    }
}

// ---------------- top-40 per row: 4-pass radix select + exact jax ordering ----------------
__global__ __launch_bounds__(256) void k_topk(){
    __shared__ int hist[256];
    __shared__ int s_nextb, s_nextneed;
    __shared__ int s_cnt, s_eqcnt;
    __shared__ uint32_t s_selu[KNN];
    __shared__ int      s_seli[KNN];
    __shared__ int      s_eq[64];

    int n = blockIdx.x;
    int t = threadIdx.x;
    const float* row = g_dist + (size_t)n*N_PTS;

    uint32_t u[8];
    #pragma unroll
    for(int i = 0; i < 8; i++){
        uint32_t b = __float_as_uint(row[t + 256*i]);
        u[i] = (b & 0x80000000u) ? ~b : (b | 0x80000000u);
    }

    uint32_t prefix = 0, mask = 0;
    int need = KNN;
    #pragma unroll
    for(int pass = 0; pass < 4; pass++){
        int shift = 24 - pass*8;
        hist[t] = 0;
        __syncthreads();
        #pragma unroll
        for(int i = 0; i < 8; i++)
            if((u[i] & mask) == prefix) atomicAdd(&hist[(u[i] >> shift) & 0xFF], 1);
        __syncthreads();
        int v = hist[t];
        for(int off = 1; off < 256; off <<= 1){
            int w = (t + off < 256) ? hist[t + off] : 0;
            __syncthreads();
            v += w; hist[t] = v;
            __syncthreads();
        }
        int Sn = (t < 255) ? hist[t + 1] : 0;
        if(v >= need && Sn < need){ s_nextb = t; s_nextneed = need - Sn; }
        __syncthreads();
        prefix |= ((uint32_t)s_nextb) << shift;
        mask   |= 0xFFu << shift;
        need = s_nextneed;
        __syncthreads();
    }
    if(t == 0){ s_cnt = 0; s_eqcnt = 0; }
    __syncthreads();
    #pragma unroll
    for(int i = 0; i < 8; i++){
        if(u[i] > prefix){
            int p = atomicAdd(&s_cnt, 1);
            s_selu[p] = u[i]; s_seli[p] = t + 256*i;
        } else if(u[i] == prefix){
            int p = atomicAdd(&s_eqcnt, 1);
            if(p < 64) s_eq[p] = t + 256*i;
        }
    }
    __syncthreads();
    if(t == 0){
        int cnt = s_cnt;
        int e = s_eqcnt < 64 ? s_eqcnt : 64;
        for(int j = 0; j < need; j++){
            int best = 0x7FFFFFFF, bi = -1;
            for(int q = 0; q < e; q++)
                if(s_eq[q] < best){ best = s_eq[q]; bi = q; }
            s_selu[cnt + j] = prefix; s_seli[cnt + j] = best;
            s_eq[bi] = 0x7FFFFFFF;
        }
    }
    __syncthreads();
    if(t < KNN){
        uint32_t mu = s_selu[t]; int mi = s_seli[t];
        int rank = 0;
        #pragma unroll
        for(int q = 0; q < KNN; q++){
            uint32_t qu = s_selu[q]; int qi = s_seli[q];
            rank += (qu > mu) || (qu == mu && qi < mi);
        }
        g_idx[n*KNN + rank] = mi;
    }
}

// ---------------- w5 split (once): fold bn5 scale; fp16 hi/lo; also tt ----------------
__global__ void k_w5split(const float* __restrict__ w5, const float* __restrict__ g5,
                          const float* __restrict__ b5, const float* __restrict__ m5,
                          const float* __restrict__ v5){
    int i = blockIdx.x*256 + threadIdx.x;
    if(i >= C5*C_IN) return;
    int o = i >> 9, c = i & 511;
    float s = g5[o]*rsqrtf(v5[o] + 1e-5f);
    float wa = s*w5[(size_t)o*1024 + c];
    float wd = s*(w5[(size_t)o*1024 + 512 + c] - w5[(size_t)o*1024 + c]);
    __half h;
    h = __float2half(wa); g_w5ahi[i] = h; g_w5alo[i] = __float2half(wa - __half2float(h));
    h = __float2half(wd); g_w5dhi[i] = h; g_w5dlo[i] = __float2half(wd - __half2float(h));
    if(c == 0) g_tt[o] = b5[o] - m5[o]*s;
}

// ---------------- x transpose+split: [c][n] fp32 -> [n][c] fp16 hi/lo ----------------
__global__ __launch_bounds__(256) void k_xsplit(const float* __restrict__ x){
    __shared__ float tile[32][33];
    int n0 = blockIdx.x*32, c0 = blockIdx.y*32;
    int tid = threadIdx.x;
    int a = tid >> 5, b = tid & 31;
    #pragma unroll
    for(int p = 0; p < 4; p++){
        int cl = p*8 + a;
        tile[cl][b] = x[(size_t)(c0+cl)*N_PTS + n0 + b];
    }
    __syncthreads();
    #pragma unroll
    for(int p = 0; p < 4; p++){
        int nl = p*8 + a;
        float v = tile[b][nl];
        __half h = __float2half(v);
        size_t o = (size_t)(n0+nl)*C_IN + c0 + b;
        g_xhi[o] = h;
        g_xlo[o] = __float2half(v - __half2float(h));
    }
}

// ---------------- w6 -> single fp16 ----------------
__global__ void k_w6split(const float* __restrict__ w6){
    int i = blockIdx.x*256 + threadIdx.x;
    if(i < C6*N_PTS) g_w6h[i] = __float2half(w6[i]);
}

// ---------------- build Lt[col][n] fp16 hi/lo (transposed, split) ----------------
__global__ __launch_bounds__(256) void k_buildLt(){
    __shared__ uint32_t sbuf[32][257];
    int k  = blockIdx.x;
    int n0 = blockIdx.y*32;
    int tid = threadIdx.x, wid = tid>>5, lane = tid&31;
    for(int half = 0; half < 2; half++){
        int c0 = half*256;
        #pragma unroll
        for(int q = 0; q < 4; q++){
            int nloc = wid*4 + q;
            int n = n0 + nloc;
            int j = g_idx[n*KNN + k];
            for(int c = lane; c < 256; c += 32){
                float v = g_At[(size_t)j*C5 + c0 + c] + g_Ct[(size_t)n*C5 + c0 + c] + g_tt[c0 + c];
                v = lrelu(v);
                __half h = __float2half(v);
                __half l = __float2half(v - __half2float(h));
                sbuf[nloc][c] = (uint32_t)__half_as_ushort(h) | ((uint32_t)__half_as_ushort(l) << 16);
            }
        }
        __syncthreads();
        for(int c = wid; c < 256; c += 8){
            uint32_t u = sbuf[lane][c];
            size_t row = (size_t)(k*C5 + c0 + c);
            g_Lthi[row*N_PTS + n0 + lane] = __ushort_as_half((unsigned short)(u & 0xFFFFu));
            g_Ltlo[row*N_PTS + n0 + lane] = __ushort_as_half((unsigned short)(u >> 16));
        }
        __syncthreads();
    }
}

// ============ unified warp-MMA fp16 split GEMM: C[m][n] = sum_k A[m,k]*B[n,k] ============
// three=1: 3-term (Ah*Bh + Ah*Bl + Al*Bh); three=0: 2-term (Ah*Bh + Ah*Bl), A single fp16
#define GM_PITCHB 80
#define GM_AOFF   0
#define GM_BOFF   20480
#define GM_STG    40960
#define GM_SMEM   (2*GM_STG)

__device__ __forceinline__ void gm_load_chunk(uint32_t sb, int s,
        const __half* Ahi, const __half* Alo,
        const __half* Bhi, const __half* Blo,
        int lda, int ldb, int m0, int n0, int ck, int tid, int three){
    uint32_t base = sb + s*GM_STG;
    int na = three ? 4 : 2;
    #pragma unroll
    for(int p = 0; p < 4; p++){
        if(p >= na) break;
        int u = p*256 + tid;
        int hl = u >> 9, rem = u & 511, row = rem >> 2, seg = rem & 3;
        const __half* src = (hl ? Alo : Ahi) + (size_t)(m0+row)*lda + ck*32 + seg*8;
        cpa16(base + GM_AOFF + hl*10240 + row*GM_PITCHB + seg*16, src);
    }
    #pragma unroll
    for(int p = 0; p < 4; p++){
        int u = p*256 + tid;
        int hl = u >> 9, rem = u & 511, row = rem >> 2, seg = rem & 3;
        const __half* src = (hl ? Blo : Bhi) + (size_t)(n0+row)*ldb + ck*32 + seg*8;
        cpa16(base + GM_BOFF + hl*10240 + row*GM_PITCHB + seg*16, src);
    }
}

__global__ void __launch_bounds__(256, 1) gemm_f16split(
        const __half* __restrict__ Ahi, const __half* __restrict__ Alo,
        const __half* __restrict__ Bhi, const __half* __restrict__ Blo,
        float* __restrict__ C, int nch, int lda, int ldb, size_t ldc, int Mlim, int three){
    extern __shared__ __align__(128) char smem[];
    uint32_t sb = smem_u32(smem);
    int tid = threadIdx.x, lane = tid & 31, wid = tid >> 5;
    int wm = wid & 3, wn = wid >> 2;
    int m0 = blockIdx.x*128, n0 = blockIdx.y*128;

    float acc[2][8][4];
    #pragma unroll
    for(int i = 0; i < 2; i++)
        #pragma unroll
        for(int j = 0; j < 8; j++)
            #pragma unroll
            for(int q = 0; q < 4; q++) acc[i][j][q] = 0.f;

    gm_load_chunk(sb, 0, Ahi, Alo, Bhi, Blo, lda, ldb, m0, n0, 0, tid, three);
    CPA_COMMIT();

    int a_row = wm*32 + (lane & 15);
    int a_col2 = ((lane >> 4) * 8) * 2;
    int b_row = wn*64 + (lane & 7) + ((lane >> 4) << 3);
    int b_col2 = (((lane >> 3) & 1) * 8) * 2;

    for(int c = 0; c < nch; c++){
        if(c + 1 < nch){
            gm_load_chunk(sb, (c+1)&1, Ahi, Alo, Bhi, Blo, lda, ldb, m0, n0, c+1, tid, three);
            CPA_COMMIT();
            CPA_WAIT1();
        } else {
            CPA_WAIT0();
        }
        __syncthreads();

        uint32_t base = sb + (c&1)*GM_STG;
        #pragma unroll
        for(int h = 0; h < 2; h++){
            int kb2 = h*16*2;
            uint32_t ah[2][4], al[2][4];
            #pragma unroll
            for(int mt = 0; mt < 2; mt++){
                uint32_t ad = base + GM_AOFF + (a_row + mt*16)*GM_PITCHB + a_col2 + kb2;
                LDM4(ah[mt], ad);
                if(three) LDM4(al[mt], ad + 10240);
            }
            uint32_t bh[8][2], bl[8][2];
            #pragma unroll
            for(int np = 0; np < 4; np++){
                uint32_t bd = base + GM_BOFF + (b_row + np*16)*GM_PITCHB + b_col2 + kb2;
                uint32_t r[4];
                LDM4(r, bd);
                bh[np*2][0] = r[0]; bh[np*2][1] = r[1]; bh[np*2+1][0] = r[2]; bh[np*2+1][1] = r[3];
                LDM4(r, bd + 10240);
                bl[np*2][0] = r[0]; bl[np*2][1] = r[1]; bl[np*2+1][0] = r[2]; bl[np*2+1][1] = r[3];
            }
            #pragma unroll
            for(int mt = 0; mt < 2; mt++)
                #pragma unroll
                for(int nt = 0; nt < 8; nt++){
                    MMA_F16(acc[mt][nt], ah[mt], bh[nt]);
                    MMA_F16(acc[mt][nt], ah[mt], bl[nt]);
                    if(three) MMA_F16(acc[mt][nt], al[mt], bh[nt]);
                }
        }
        __syncthreads();
    }

    int g = lane >> 2, tg = lane & 3;
    #pragma unroll
    for(int mt = 0; mt < 2; mt++){
        int m = m0 + wm*32 + mt*16 + g;
        #pragma unroll
        for(int nt = 0; nt < 8; nt++){
            int col = n0 + wn*64 + nt*8 + tg*2;
            if(m < Mlim)
                *(float2*)(C + (size_t)m*ldc + col) = make_float2(acc[mt][nt][0], acc[mt][nt][1]);
            if(m + 8 < Mlim)
                *(float2*)(C + (size_t)(m+8)*ldc + col) = make_float2(acc[mt][nt][2], acc[mt][nt][3]);
        }
    }
}

// ---------------- generic gemm_nn (attention tail) ----------------
__global__ __launch_bounds__(256) void gemm_nn(const float* __restrict__ A, const float* __restrict__ B,
                       float* __restrict__ C, int M, int N, int K,
                       int lda, int ldb, int ldc,
                       long long sA, long long sB, long long sC){
    A += (size_t)blockIdx.z * sA; B += (size_t)blockIdx.z * sB; C += (size_t)blockIdx.z * sC;
    __shared__ float sAp[64][17];
    __shared__ __align__(16) float sBt[16][64];
    int tx = threadIdx.x, ty = threadIdx.y, t = ty*16 + tx;
    int m0 = blockIdx.y*64, n0 = blockIdx.x*64;
    float acc[4][4] = {};
    for(int k0 = 0; k0 < K; k0 += 16){
        #pragma unroll
        for(int i = 0; i < 4; i++){
            int e = t + i*256; int kt = e & 15; int mi = e >> 4;
            int m = m0 + mi, k = k0 + kt;
            sAp[mi][kt] = (m < M && k < K) ? A[(size_t)m*lda + k] : 0.f;
        }
        #pragma unroll
        for(int i = 0; i < 4; i++){
            int e = t + i*256; int ni = e & 63; int kt = e >> 6;
            int k = k0 + kt, n = n0 + ni;
            sBt[kt][ni] = (k < K && n < N) ? B[(size_t)k*ldb + n] : 0.f;
        }
        __syncthreads();
        #pragma unroll
        for(int kk = 0; kk < 16; kk++){
            float av[4];
            #pragma unroll
            for(int i = 0; i < 4; i++) av[i] = sAp[ty*4+i][kk];
            float4 b4 = *(const float4*)&sBt[kk][tx*4];
            float bv[4] = {b4.x,b4.y,b4.z,b4.w};
            #pragma unroll
            for(int i = 0; i < 4; i++)
                #pragma unroll
                for(int j = 0; j < 4; j++) acc[i][j] += av[i]*bv[j];
        }
        __syncthreads();
    }
    #pragma unroll
    for(int i = 0; i < 4; i++){
        int m = m0 + ty*4 + i; if(m >= M) continue;
        #pragma unroll
        for(int j = 0; j < 4; j++){
            int n = n0 + tx*4 + j; if(n >= N) continue;
            C[(size_t)m*ldc + n] = acc[i][j];
        }
    }
}

// ---------------- generic gemm_nt (+bias) ----------------
__global__ __launch_bounds__(256) void gemm_nt(const float* __restrict__ A, const float* __restrict__ B,
                       float* __restrict__ C, int M, int N, int K,
                       int lda, int ldb, int ldc,
                       long long sA, long long sB, long long sC,
                       const float* __restrict__ bias){
    A += (size_t)blockIdx.z * sA; B += (size_t)blockIdx.z * sB; C += (size_t)blockIdx.z * sC;
    __shared__ float sAp[64][17];
    __shared__ float sBp[64][17];
    int tx = threadIdx.x, ty = threadIdx.y, t = ty*16 + tx;
    int m0 = blockIdx.y*64, n0 = blockIdx.x*64;
    float acc[4][4] = {};
    for(int k0 = 0; k0 < K; k0 += 16){
        #pragma unroll
        for(int i = 0; i < 4; i++){
            int e = t + i*256; int kt = e & 15; int mi = e >> 4;
            int m = m0 + mi, k = k0 + kt;
            sAp[mi][kt] = (m < M && k < K) ? A[(size_t)m*lda + k] : 0.f;
        }
        #pragma unroll
        for(int i = 0; i < 4; i++){
            int e = t + i*256; int kt = e & 15; int ni = e >> 4;
            int n = n0 + ni, k = k0 + kt;
            sBp[ni][kt] = (n < N && k < K) ? B[(size_t)n*ldb + k] : 0.f;
        }
        __syncthreads();
        #pragma unroll
        for(int kk = 0; kk < 16; kk++){
            float av[4], bv[4];
            #pragma unroll
            for(int i = 0; i < 4; i++) av[i] = sAp[ty*4+i][kk];
            #pragma unroll
            for(int j = 0; j < 4; j++) bv[j] = sBp[tx*4+j][kk];
            #pragma unroll
            for(int i = 0; i < 4; i++)
                #pragma unroll
                for(int j = 0; j < 4; j++) acc[i][j] += av[i]*bv[j];
        }
        __syncthreads();
    }
    #pragma unroll
    for(int i = 0; i < 4; i++){
        int m = m0 + ty*4 + i; if(m >= M) continue;
        #pragma unroll
        for(int j = 0; j < 4; j++){
            int n = n0 + tx*4 + j; if(n >= N) continue;
            float bb = bias ? bias[n] : 0.f;
            C[(size_t)m*ldc + n] = acc[i][j] + bb;
        }
    }
}

// ---------------- bn6 + lrelu + max over k ----------------
__global__ void k_maxpool(const float* __restrict__ g6, const float* __restrict__ b6,
                          const float* __restrict__ m6, const float* __restrict__ v6,
                          float* __restrict__ f){
    int o = blockIdx.y;
    int c = blockIdx.x*256 + threadIdx.x;
    float s = g6[o]*rsqrtf(v6[o] + 1e-5f);
    float t = b6[o] - m6[o]*s;
    const float* row = g_o2 + (size_t)o*NKCOL + c;
    float mx = -INFINITY;
    #pragma unroll 8
    for(int k = 0; k < KNN; k++){
        float h = s*row[(size_t)k*C5] + t;
        h = lrelu(h);
        mx = fmaxf(mx, h);
    }
    f[(size_t)c*C6 + o] = mx;
}

// ---------------- row softmax ----------------
__global__ __launch_bounds__(256) void k_softmax(){
    int r = blockIdx.x;
    float* p = g_sc + (size_t)r*C5;
    __shared__ float red[256];
    int t = threadIdx.x;
    float v0 = p[t]*SOFT_SCALE, v1 = p[t+256]*SOFT_SCALE;
    red[t] = fmaxf(v0, v1); __syncthreads();
    for(int s = 128; s > 0; s >>= 1){ if(t < s) red[t] = fmaxf(red[t], red[t+s]); __syncthreads(); }
    float mm = red[0]; __syncthreads();
    float e0 = __expf(v0 - mm), e1 = __expf(v1 - mm);
    red[t] = e0 + e1; __syncthreads();
    for(int s = 128; s > 0; s >>= 1){ if(t < s) red[t] += red[t+s]; __syncthreads(); }
    float inv = 1.f/red[0];
    p[t] = e0*inv; p[t+256] = e1*inv;
}

// =============================== host launcher ===============================
extern "C" void kernel_launch(void* const* d_in, const int* in_sizes, int n_in,
                              void* d_out, int out_size){
    const float* x    = (const float*)d_in[0];
    const float* y    = (const float*)d_in[1];
    const float* w5   = (const float*)d_in[2];
    const float* g5   = (const float*)d_in[3];
    const float* b5   = (const float*)d_in[4];
    const float* m5   = (const float*)d_in[5];
    const float* v5   = (const float*)d_in[6];
    const float* w6   = (const float*)d_in[7];
    const float* g6   = (const float*)d_in[8];
    const float* b6   = (const float*)d_in[9];
    const float* m6   = (const float*)d_in[10];
    const float* v6   = (const float*)d_in[11];
    const float* Wq   = (const float*)d_in[12];
    const float* Wk   = (const float*)d_in[13];
    const float* Wv   = (const float*)d_in[14];
    const float* Wout = (const float*)d_in[15];
    const float* bout = (const float*)d_in[16];
    float* out = (float*)d_out;

    float *pxf, *pyf, *pq, *pk, *pv, *psc, *pm, *pAt, *pCt, *pO2;
    __half *pxhi, *pxlo, *pw5ahi, *pw5alo, *pw5dhi, *pw5dlo, *pw6h, *pLthi, *pLtlo;
    cudaGetSymbolAddress((void**)&pxf, g_xf);
    cudaGetSymbolAddress((void**)&pyf, g_yf);
    cudaGetSymbolAddress((void**)&pq,  g_q);
    cudaGetSymbolAddress((void**)&pk,  g_k);
    cudaGetSymbolAddress((void**)&pv,  g_v);
    cudaGetSymbolAddress((void**)&psc, g_sc);
    cudaGetSymbolAddress((void**)&pm,  g_mg);
    cudaGetSymbolAddress((void**)&pAt, g_At);
    cudaGetSymbolAddress((void**)&pCt, g_Ct);
    cudaGetSymbolAddress((void**)&pO2, g_o2);
    cudaGetSymbolAddress((void**)&pxhi, g_xhi);
    cudaGetSymbolAddress((void**)&pxlo, g_xlo);
    cudaGetSymbolAddress((void**)&pw5ahi, g_w5ahi);
    cudaGetSymbolAddress((void**)&pw5alo, g_w5alo);
    cudaGetSymbolAddress((void**)&pw5dhi, g_w5dhi);
    cudaGetSymbolAddress((void**)&pw5dlo, g_w5dlo);
    cudaGetSymbolAddress((void**)&pw6h, g_w6h);
    cudaGetSymbolAddress((void**)&pLthi, g_Lthi);
    cudaGetSymbolAddress((void**)&pLtlo, g_Ltlo);

    cudaFuncSetAttribute(gemm_f16split, cudaFuncAttributeMaxDynamicSharedMemorySize, GM_SMEM);

    dim3 t2(16, 16);

    k_w6split<<<(C6*N_PTS + 255)/256, 256>>>(w6);
    k_w5split<<<(C5*C_IN + 255)/256, 256>>>(w5, g5, b5, m5, v5);

    for(int br = 0; br < 2; br++){
        const float* p = br ? y : x;
        float* f = br ? pyf : pxf;

        k_xx<<<8, 256>>>(p);
        k_dist<<<528, t2>>>(p);
        k_topk<<<N_PTS, 256>>>();
        k_xsplit<<<dim3(64, 16), 256>>>(p);
        // At[n][o] = (s5*w5a) @ x ; Ct[n][o] = (s5*(w5b-w5a)) @ x   (3-term fp16)
        gemm_f16split<<<dim3(16, 4), 256, GM_SMEM>>>(pxhi, pxlo, pw5ahi, pw5alo,
                pAt, C_IN/32, C_IN, C_IN, (size_t)C5, N_PTS, 1);
        gemm_f16split<<<dim3(16, 4), 256, GM_SMEM>>>(pxhi, pxlo, pw5dhi, pw5dlo,
                pCt, C_IN/32, C_IN, C_IN, (size_t)C5, N_PTS, 1);
        k_buildLt<<<dim3(KNN, 64), 256>>>();
        // out2 = w6 @ L   (2-term fp16: A single, B hi/lo)
        gemm_f16split<<<dim3(5, 160), 256, GM_SMEM>>>(pw6h, pw6h, pLthi, pLtlo,
                pO2, N_PTS/32, N_PTS, N_PTS, (size_t)NKCOL, C6, 0);
        k_maxpool<<<dim3(2, C6), 256>>>(g6, b6, m6, v6, f);
    }

    // q/k/v
    gemm_nt<<<dim3(8, 8, 1), t2>>>(pxf, Wq, pq, C5, HD, INDIM, INDIM, INDIM, HD, 0, 0, 0, nullptr);
    gemm_nt<<<dim3(8, 8, 1), t2>>>(pyf, Wk, pk, C5, HD, INDIM, INDIM, INDIM, HD, 0, 0, 0, nullptr);
    gemm_nt<<<dim3(8, 8, 1), t2>>>(pyf, Wv, pv, C5, HD, INDIM, INDIM, INDIM, HD, 0, 0, 0, nullptr);

    // scores
    gemm_nt<<<dim3(8, 8, NH), t2>>>(pq, pk, psc, C5, C5, AD, HD, HD, C5,
                                    AD, AD, (long long)C5*C5, nullptr);
    k_softmax<<<NH*C5, 256>>>();

    // weighted
    gemm_nn<<<dim3(1, 8, NH), t2>>>(psc, pv, pm, C5, AD, C5, C5, HD, HD,
                                    (long long)C5*C5, AD, AD);

    // output projection
    gemm_nt<<<dim3((C6+63)/64, 8, 1), t2>>>(pm, Wout, out, C5, C6, HD, HD, HD, C6,
                                            0, 0, 0, bout);
}

// round 14
// speedup vs baseline: 3.8932x; 1.6996x over previous
#include <cuda_runtime.h>
#include <cuda_fp16.h>
#include <math.h>
#include <stdint.h>

#define N_PTS 2048
#define C_IN  512
#define KNN   40
#define C5    512
#define C6    515
#define INDIM C6
#define NKCOL (KNN*C5)         // 20480
#define HD    512
#define NH    8
#define AD    64
#define M_PAD 640
#define SOFT_SCALE 0.04419417382415922f

// ---------------- scratch (device globals, no runtime alloc) ----------------
__device__ float g_dist[(size_t)N_PTS*N_PTS];
__device__ int   g_idx[N_PTS*KNN];
__device__ float g_xx[N_PTS];
__device__ float g_At[(size_t)N_PTS*C5];
__device__ float g_Ct[(size_t)N_PTS*C5];
__device__ float g_tt[C5];
__device__ __half g_xhi[(size_t)N_PTS*C_IN];
__device__ __half g_xlo[(size_t)N_PTS*C_IN];
__device__ __half g_w5ahi[C5*C_IN];
__device__ __half g_w5alo[C5*C_IN];
__device__ __half g_w5dhi[C5*C_IN];
__device__ __half g_w5dlo[C5*C_IN];
__device__ __half g_w6h[(size_t)M_PAD*N_PTS];        // w6 single fp16 [o][n]
__device__ __half g_Lth[(size_t)NKCOL*N_PTS];        // L single fp16 [col][n] (84 MB)
__device__ float g_o2[(size_t)C6*NKCOL];
__device__ float g_xf[C5*C6];
__device__ float g_yf[C5*C6];
__device__ float g_q [C5*HD];
__device__ float g_k [C5*HD];
__device__ float g_v [C5*HD];
__device__ float g_sc[(size_t)NH*C5*C5];
__device__ float g_mg[C5*HD];

__device__ __forceinline__ float lrelu(float v){ return v > 0.f ? v : 0.2f*v; }

// ====================== PTX helpers (baseline sm_80+) ======================
__device__ __forceinline__ uint32_t smem_u32(const void* p){
    uint32_t a;
    asm("{ .reg .u64 t; cvta.to.shared.u64 t, %1; cvt.u32.u64 %0, t; }" : "=r"(a) : "l"(p));
    return a;
}
__device__ __forceinline__ void cpa16(uint32_t dst, const void* src){
    asm volatile("cp.async.cg.shared.global [%0], [%1], 16;" :: "r"(dst), "l"(src));
}
#define CPA_COMMIT() asm volatile("cp.async.commit_group;" ::: "memory")
#define CPA_WAIT1()  asm volatile("cp.async.wait_group 1;" ::: "memory")
#define CPA_WAIT0()  asm volatile("cp.async.wait_group 0;" ::: "memory")

#define LDM4(r, ad) \
    asm volatile("ldmatrix.sync.aligned.m8n8.x4.shared.b16 {%0,%1,%2,%3}, [%4];" \
        : "=r"((r)[0]), "=r"((r)[1]), "=r"((r)[2]), "=r"((r)[3]) : "r"(ad))

#define MMA_F16(d, a, b) \
    asm volatile("mma.sync.aligned.m16n8k16.row.col.f32.f16.f16.f32 " \
        "{%0,%1,%2,%3},{%4,%5,%6,%7},{%8,%9},{%0,%1,%2,%3};" \
        : "+f"((d)[0]), "+f"((d)[1]), "+f"((d)[2]), "+f"((d)[3]) \
        : "r"((a)[0]), "r"((a)[1]), "r"((a)[2]), "r"((a)[3]), "r"((b)[0]), "r"((b)[1]))

// ---------------- xx[n] = sum_c x[c,n]^2 ----------------
__global__ void k_xx(const float* __restrict__ x){
    int n = blockIdx.x*blockDim.x + threadIdx.x;
    if(n < N_PTS){
        float s = 0.f;
        for(int c = 0; c < C_IN; c++){ float v = x[(size_t)c*N_PTS + n]; s += v*v; }
        g_xx[n] = s;
    }
}

// ---------------- neg sq dist, symmetric, triangular grid ----------------
__global__ __launch_bounds__(256) void k_dist(const float* __restrict__ x){
    int bi = blockIdx.x;
    int by = (int)((sqrtf(8.f*bi + 1.f) - 1.f)*0.5f);
    while(((by + 1)*(by + 2))/2 <= bi) ++by;
    while((by*(by + 1))/2 > bi) --by;
    int bx = bi - (by*(by + 1))/2;

    __shared__ __align__(16) float sN[16][64];
    __shared__ __align__(16) float sM[16][64];
    int tx = threadIdx.x, ty = threadIdx.y, t = ty*16 + tx;
    int n0 = by*64, m0 = bx*64;
    float acc[4][4] = {};
    for(int c0 = 0; c0 < C_IN; c0 += 16){
        #pragma unroll
        for(int i = 0; i < 4; i++){
            int e = t + i*256; int kt = e >> 6; int col = e & 63;
            sN[kt][col] = x[(size_t)(c0+kt)*N_PTS + n0 + col];
            sM[kt][col] = x[(size_t)(c0+kt)*N_PTS + m0 + col];
        }
        __syncthreads();
        #pragma unroll
        for(int kk = 0; kk < 16; kk++){
            float4 a4 = *(const float4*)&sN[kk][ty*4];
            float4 b4 = *(const float4*)&sM[kk][tx*4];
            float av[4] = {a4.x,a4.y,a4.z,a4.w};
            float bv[4] = {b4.x,b4.y,b4.z,b4.w};
            #pragma unroll
            for(int i = 0; i < 4; i++)
                #pragma unroll
                for(int j = 0; j < 4; j++) acc[i][j] += av[i]*bv[j];
        }
        __syncthreads();
    }
    float xnv[4], xmv[4], v[4][4];
    #pragma unroll
    for(int i = 0; i < 4; i++) xnv[i] = g_xx[n0 + ty*4 + i];
    #pragma unroll
    for(int j = 0; j < 4; j++) xmv[j] = g_xx[m0 + tx*4 + j];
    #pragma unroll
    for(int i = 0; i < 4; i++)
        #pragma unroll
        for(int j = 0; j < 4; j++) v[i][j] = 2.f*acc[i][j] - xnv[i] - xmv[j];
    #pragma unroll
    for(int i = 0; i < 4; i++){
        float4 w = make_float4(v[i][0], v[i][1], v[i][2], v[i][3]);
        *(float4*)&g_dist[(size_t)(n0 + ty*4 + i)*N_PTS + m0 + tx*4] = w;
    }
    if(bx != by){
        #pragma unroll
        for(int j = 0; j < 4; j++){
            float4 w = make_float4(v[0][j], v[1][j], v[2][j], v[3][j]);
            *(float4*)&g_dist[(size_t)(m0 + tx*4 + j)*N_PTS + n0 + ty*4] = w;
        }
    }
}

// ---------------- top-40 per row: radix select + exact jax ordering ----------------
__global__ __launch_bounds__(256) void k_topk(){
    __shared__ int hist[256];
    __shared__ int s_nextb, s_nextneed;
    __shared__ int s_cnt, s_eqcnt;
    __shared__ uint32_t s_selu[KNN];
    __shared__ int      s_seli[KNN];
    __shared__ int      s_eq[64];

    int n = blockIdx.x;
    int t = threadIdx.x;
    const float* row = g_dist + (size_t)n*N_PTS;

    uint32_t u[8];
    #pragma unroll
    for(int i = 0; i < 8; i++){
        uint32_t b = __float_as_uint(row[t + 256*i]);
        u[i] = (b & 0x80000000u) ? ~b : (b | 0x80000000u);
    }

    uint32_t prefix = 0, mask = 0;
    int need = KNN;
    #pragma unroll
    for(int pass = 0; pass < 4; pass++){
        int shift = 24 - pass*8;
        hist[t] = 0;
        __syncthreads();
        #pragma unroll
        for(int i = 0; i < 8; i++)
            if((u[i] & mask) == prefix) atomicAdd(&hist[(u[i] >> shift) & 0xFF], 1);
        __syncthreads();
        int v = hist[t];
        for(int off = 1; off < 256; off <<= 1){
            int w = (t + off < 256) ? hist[t + off] : 0;
            __syncthreads();
            v += w; hist[t] = v;
            __syncthreads();
        }
        int Sn = (t < 255) ? hist[t + 1] : 0;
        if(v >= need && Sn < need){ s_nextb = t; s_nextneed = need - Sn; }
        __syncthreads();
        prefix |= ((uint32_t)s_nextb) << shift;
        mask   |= 0xFFu << shift;
        need = s_nextneed;
        __syncthreads();
    }
    if(t == 0){ s_cnt = 0; s_eqcnt = 0; }
    __syncthreads();
    #pragma unroll
    for(int i = 0; i < 8; i++){
        if(u[i] > prefix){
            int p = atomicAdd(&s_cnt, 1);
            s_selu[p] = u[i]; s_seli[p] = t + 256*i;
        } else if(u[i] == prefix){
            int p = atomicAdd(&s_eqcnt, 1);
            if(p < 64) s_eq[p] = t + 256*i;
        }
    }
    __syncthreads();
    if(t == 0){
        int cnt = s_cnt;
        int e = s_eqcnt < 64 ? s_eqcnt : 64;
        for(int j = 0; j < need; j++){
            int best = 0x7FFFFFFF, bi = -1;
            for(int q = 0; q < e; q++)
                if(s_eq[q] < best){ best = s_eq[q]; bi = q; }
            s_selu[cnt + j] = prefix; s_seli[cnt + j] = best;
            s_eq[bi] = 0x7FFFFFFF;
        }
    }
    __syncthreads();
    if(t < KNN){
        uint32_t mu = s_selu[t]; int mi = s_seli[t];
        int rank = 0;
        #pragma unroll
        for(int q = 0; q < KNN; q++){
            uint32_t qu = s_selu[q]; int qi = s_seli[q];
            rank += (qu > mu) || (qu == mu && qi < mi);
        }
        g_idx[n*KNN + rank] = mi;
    }
}

// ---------------- w5 split (once): fold bn5 scale; fp16 hi/lo; also tt ----------------
__global__ void k_w5split(const float* __restrict__ w5, const float* __restrict__ g5,
                          const float* __restrict__ b5, const float* __restrict__ m5,
                          const float* __restrict__ v5){
    int i = blockIdx.x*256 + threadIdx.x;
    if(i >= C5*C_IN) return;
    int o = i >> 9, c = i & 511;
    float s = g5[o]*rsqrtf(v5[o] + 1e-5f);
    float wa = s*w5[(size_t)o*1024 + c];
    float wd = s*(w5[(size_t)o*1024 + 512 + c] - w5[(size_t)o*1024 + c]);
    __half h;
    h = __float2half(wa); g_w5ahi[i] = h; g_w5alo[i] = __float2half(wa - __half2float(h));
    h = __float2half(wd); g_w5dhi[i] = h; g_w5dlo[i] = __float2half(wd - __half2float(h));
    if(c == 0) g_tt[o] = b5[o] - m5[o]*s;
}

// ---------------- x transpose+split: [c][n] fp32 -> [n][c] fp16 hi/lo ----------------
__global__ __launch_bounds__(256) void k_xsplit(const float* __restrict__ x){
    __shared__ float tile[32][33];
    int n0 = blockIdx.x*32, c0 = blockIdx.y*32;
    int tid = threadIdx.x;
    int a = tid >> 5, b = tid & 31;
    #pragma unroll
    for(int p = 0; p < 4; p++){
        int cl = p*8 + a;
        tile[cl][b] = x[(size_t)(c0+cl)*N_PTS + n0 + b];
    }
    __syncthreads();
    #pragma unroll
    for(int p = 0; p < 4; p++){
        int nl = p*8 + a;
        float v = tile[b][nl];
        __half h = __float2half(v);
        size_t o = (size_t)(n0+nl)*C_IN + c0 + b;
        g_xhi[o] = h;
        g_xlo[o] = __float2half(v - __half2float(h));
    }
}

// ---------------- w6 -> single fp16 ----------------
__global__ void k_w6split(const float* __restrict__ w6){
    int i = blockIdx.x*256 + threadIdx.x;
    if(i < C6*N_PTS) g_w6h[i] = __float2half(w6[i]);
}

// ---------------- build Lt[col][n] single fp16 (transposed) ----------------
__global__ __launch_bounds__(256) void k_buildLt(){
    __shared__ uint32_t sbuf[32][257];
    int k  = blockIdx.x;
    int n0 = blockIdx.y*32;
    int tid = threadIdx.x, wid = tid>>5, lane = tid&31;
    for(int half = 0; half < 2; half++){
        int c0 = half*256;
        #pragma unroll
        for(int q = 0; q < 4; q++){
            int nloc = wid*4 + q;
            int n = n0 + nloc;
            int j = g_idx[n*KNN + k];
            for(int c = lane; c < 256; c += 32){
                float v = g_At[(size_t)j*C5 + c0 + c] + g_Ct[(size_t)n*C5 + c0 + c] + g_tt[c0 + c];
                v = lrelu(v);
                sbuf[nloc][c] = (uint32_t)__half_as_ushort(__float2half(v));
            }
        }
        __syncthreads();
        for(int c = wid; c < 256; c += 8){
            size_t row = (size_t)(k*C5 + c0 + c);
            g_Lth[row*N_PTS + n0 + lane] = __ushort_as_half((unsigned short)(sbuf[lane][c] & 0xFFFFu));
        }
        __syncthreads();
    }
}

// ============ templated warp-MMA fp16 GEMM: C[m][n] = sum_k A[m,k]*B[n,k] ============
// MODE==1: 1-term, A/B single fp16 (stage 20KB, 2 CTAs/SM)
// MODE==3: 3-term hi/lo split (stage 40KB)
#define GM_PITCHB 80

template<int MODE>
__device__ __forceinline__ void gm_load_chunk(uint32_t sb, int s,
        const __half* Ahi, const __half* Alo,
        const __half* Bhi, const __half* Blo,
        int lda, int ldb, int m0, int n0, int ck, int tid){
    constexpr int ABUF = (MODE == 3) ? 20480 : 10240;
    constexpr int BBUF = (MODE == 3) ? 20480 : 10240;
    constexpr int STG  = ABUF + BBUF;
    uint32_t base = sb + s*STG;
    #pragma unroll
    for(int p = 0; p < 2; p++){
        int u = p*256 + tid; int row = u >> 2, seg = u & 3;
        cpa16(base + row*GM_PITCHB + seg*16, Ahi + (size_t)(m0+row)*lda + ck*32 + seg*8);
    }
    if(MODE == 3){
        #pragma unroll
        for(int p = 0; p < 2; p++){
            int u = p*256 + tid; int row = u >> 2, seg = u & 3;
            cpa16(base + 10240 + row*GM_PITCHB + seg*16, Alo + (size_t)(m0+row)*lda + ck*32 + seg*8);
        }
    }
    #pragma unroll
    for(int p = 0; p < 2; p++){
        int u = p*256 + tid; int row = u >> 2, seg = u & 3;
        cpa16(base + ABUF + row*GM_PITCHB + seg*16, Bhi + (size_t)(n0+row)*ldb + ck*32 + seg*8);
    }
    if(MODE == 3){
        #pragma unroll
        for(int p = 0; p < 2; p++){
            int u = p*256 + tid; int row = u >> 2, seg = u & 3;
            cpa16(base + ABUF + 10240 + row*GM_PITCHB + seg*16, Blo + (size_t)(n0+row)*ldb + ck*32 + seg*8);
        }
    }
}

template<int MODE>
__global__ void __launch_bounds__(256, 2) gemm_f16t(
        const __half* __restrict__ Ahi, const __half* __restrict__ Alo,
        const __half* __restrict__ Bhi, const __half* __restrict__ Blo,
        float* __restrict__ C, int nch, int lda, int ldb, size_t ldc, int Mlim){
    constexpr int ABUF = (MODE == 3) ? 20480 : 10240;
    constexpr int BBUF = (MODE == 3) ? 20480 : 10240;
    constexpr int STG  = ABUF + BBUF;
    extern __shared__ __align__(128) char smem[];
    uint32_t sb = smem_u32(smem);
    int tid = threadIdx.x, lane = tid & 31, wid = tid >> 5;
    int wm = wid & 3, wn = wid >> 2;
    int m0 = blockIdx.x*128, n0 = blockIdx.y*128;

    float acc[2][8][4];
    #pragma unroll
    for(int i = 0; i < 2; i++)
        #pragma unroll
        for(int j = 0; j < 8; j++)
            #pragma unroll
            for(int q = 0; q < 4; q++) acc[i][j][q] = 0.f;

    gm_load_chunk<MODE>(sb, 0, Ahi, Alo, Bhi, Blo, lda, ldb, m0, n0, 0, tid);
    CPA_COMMIT();

    int a_row = wm*32 + (lane & 15);
    int a_col2 = ((lane >> 4) * 8) * 2;
    int b_row = wn*64 + (lane & 7) + ((lane >> 4) << 3);
    int b_col2 = (((lane >> 3) & 1) * 8) * 2;

    for(int c = 0; c < nch; c++){
        if(c + 1 < nch){
            gm_load_chunk<MODE>(sb, (c+1)&1, Ahi, Alo, Bhi, Blo, lda, ldb, m0, n0, c+1, tid);
            CPA_COMMIT();
            CPA_WAIT1();
        } else {
            CPA_WAIT0();
        }
        __syncthreads();

        uint32_t base = sb + (c&1)*STG;
        #pragma unroll
        for(int h = 0; h < 2; h++){
            int kb2 = h*16*2;
            uint32_t ah[2][4], al[2][4];
            #pragma unroll
            for(int mt = 0; mt < 2; mt++){
                uint32_t ad = base + (a_row + mt*16)*GM_PITCHB + a_col2 + kb2;
                LDM4(ah[mt], ad);
                if(MODE == 3) LDM4(al[mt], ad + 10240);
            }
            uint32_t bh[8][2], bl[8][2];
            #pragma unroll
            for(int np = 0; np < 4; np++){
                uint32_t bd = base + ABUF + (b_row + np*16)*GM_PITCHB + b_col2 + kb2;
                uint32_t r[4];
                LDM4(r, bd);
                bh[np*2][0] = r[0]; bh[np*2][1] = r[1]; bh[np*2+1][0] = r[2]; bh[np*2+1][1] = r[3];
                if(MODE == 3){
                    LDM4(r, bd + 10240);
                    bl[np*2][0] = r[0]; bl[np*2][1] = r[1]; bl[np*2+1][0] = r[2]; bl[np*2+1][1] = r[3];
                }
            }
            #pragma unroll
            for(int mt = 0; mt < 2; mt++)
                #pragma unroll
                for(int nt = 0; nt < 8; nt++){
                    MMA_F16(acc[mt][nt], ah[mt], bh[nt]);
                    if(MODE == 3){
                        MMA_F16(acc[mt][nt], ah[mt], bl[nt]);
                        MMA_F16(acc[mt][nt], al[mt], bh[nt]);
                    }
                }
        }
        __syncthreads();
    }

    int g = lane >> 2, tg = lane & 3;
    #pragma unroll
    for(int mt = 0; mt < 2; mt++){
        int m = m0 + wm*32 + mt*16 + g;
        #pragma unroll
        for(int nt = 0; nt < 8; nt++){
            int col = n0 + wn*64 + nt*8 + tg*2;
            if(m < Mlim)
                *(float2*)(C + (size_t)m*ldc + col) = make_float2(acc[mt][nt][0], acc[mt][nt][1]);
            if(m + 8 < Mlim)
                *(float2*)(C + (size_t)(m+8)*ldc + col) = make_float2(acc[mt][nt][2], acc[mt][nt][3]);
        }
    }
}

// ---------------- generic gemm_nn (attention tail) ----------------
__global__ __launch_bounds__(256) void gemm_nn(const float* __restrict__ A, const float* __restrict__ B,
                       float* __restrict__ C, int M, int N, int K,
                       int lda, int ldb, int ldc,
                       long long sA, long long sB, long long sC){
    A += (size_t)blockIdx.z * sA; B += (size_t)blockIdx.z * sB; C += (size_t)blockIdx.z * sC;
    __shared__ float sAp[64][17];
    __shared__ __align__(16) float sBt[16][64];
    int tx = threadIdx.x, ty = threadIdx.y, t = ty*16 + tx;
    int m0 = blockIdx.y*64, n0 = blockIdx.x*64;
    float acc[4][4] = {};
    for(int k0 = 0; k0 < K; k0 += 16){
        #pragma unroll
        for(int i = 0; i < 4; i++){
            int e = t + i*256; int kt = e & 15; int mi = e >> 4;
            int m = m0 + mi, k = k0 + kt;
            sAp[mi][kt] = (m < M && k < K) ? A[(size_t)m*lda + k] : 0.f;
        }
        #pragma unroll
        for(int i = 0; i < 4; i++){
            int e = t + i*256; int ni = e & 63; int kt = e >> 6;
            int k = k0 + kt, n = n0 + ni;
            sBt[kt][ni] = (k < K && n < N) ? B[(size_t)k*ldb + n] : 0.f;
        }
        __syncthreads();
        #pragma unroll
        for(int kk = 0; kk < 16; kk++){
            float av[4];
            #pragma unroll
            for(int i = 0; i < 4; i++) av[i] = sAp[ty*4+i][kk];
            float4 b4 = *(const float4*)&sBt[kk][tx*4];
            float bv[4] = {b4.x,b4.y,b4.z,b4.w};
            #pragma unroll
            for(int i = 0; i < 4; i++)
                #pragma unroll
                for(int j = 0; j < 4; j++) acc[i][j] += av[i]*bv[j];
        }
        __syncthreads();
    }
    #pragma unroll
    for(int i = 0; i < 4; i++){
        int m = m0 + ty*4 + i; if(m >= M) continue;
        #pragma unroll
        for(int j = 0; j < 4; j++){
            int n = n0 + tx*4 + j; if(n >= N) continue;
            C[(size_t)m*ldc + n] = acc[i][j];
        }
    }
}

// ---------------- generic gemm_nt (+bias) ----------------
__global__ __launch_bounds__(256) void gemm_nt(const float* __restrict__ A, const float* __restrict__ B,
                       float* __restrict__ C, int M, int N, int K,
                       int lda, int ldb, int ldc,
                       long long sA, long long sB, long long sC,
                       const float* __restrict__ bias){
    A += (size_t)blockIdx.z * sA; B += (size_t)blockIdx.z * sB; C += (size_t)blockIdx.z * sC;
    __shared__ float sAp[64][17];
    __shared__ float sBp[64][17];
    int tx = threadIdx.x, ty = threadIdx.y, t = ty*16 + tx;
    int m0 = blockIdx.y*64, n0 = blockIdx.x*64;
    float acc[4][4] = {};
    for(int k0 = 0; k0 < K; k0 += 16){
        #pragma unroll
        for(int i = 0; i < 4; i++){
            int e = t + i*256; int kt = e & 15; int mi = e >> 4;
            int m = m0 + mi, k = k0 + kt;
            sAp[mi][kt] = (m < M && k < K) ? A[(size_t)m*lda + k] : 0.f;
        }
        #pragma unroll
        for(int i = 0; i < 4; i++){
            int e = t + i*256; int kt = e & 15; int ni = e >> 4;
            int n = n0 + ni, k = k0 + kt;
            sBp[ni][kt] = (n < N && k < K) ? B[(size_t)n*ldb + k] : 0.f;
        }
        __syncthreads();
        #pragma unroll
        for(int kk = 0; kk < 16; kk++){
            float av[4], bv[4];
            #pragma unroll
            for(int i = 0; i < 4; i++) av[i] = sAp[ty*4+i][kk];
            #pragma unroll
            for(int j = 0; j < 4; j++) bv[j] = sBp[tx*4+j][kk];
            #pragma unroll
            for(int i = 0; i < 4; i++)
                #pragma unroll
                for(int j = 0; j < 4; j++) acc[i][j] += av[i]*bv[j];
        }
        __syncthreads();
    }
    #pragma unroll
    for(int i = 0; i < 4; i++){
        int m = m0 + ty*4 + i; if(m >= M) continue;
        #pragma unroll
        for(int j = 0; j < 4; j++){
            int n = n0 + tx*4 + j; if(n >= N) continue;
            float bb = bias ? bias[n] : 0.f;
            C[(size_t)m*ldc + n] = acc[i][j] + bb;
        }
    }
}

// ---------------- bn6 + lrelu + max over k ----------------
__global__ void k_maxpool(const float* __restrict__ g6, const float* __restrict__ b6,
                          const float* __restrict__ m6, const float* __restrict__ v6,
                          float* __restrict__ f){
    int o = blockIdx.y;
    int c = blockIdx.x*256 + threadIdx.x;
    float s = g6[o]*rsqrtf(v6[o] + 1e-5f);
    float t = b6[o] - m6[o]*s;
    const float* row = g_o2 + (size_t)o*NKCOL + c;
    float mx = -INFINITY;
    #pragma unroll 8
    for(int k = 0; k < KNN; k++){
        float h = s*row[(size_t)k*C5] + t;
        h = lrelu(h);
        mx = fmaxf(mx, h);
    }
    f[(size_t)c*C6 + o] = mx;
}

// ---------------- row softmax ----------------
__global__ __launch_bounds__(256) void k_softmax(){
    int r = blockIdx.x;
    float* p = g_sc + (size_t)r*C5;
    __shared__ float red[256];
    int t = threadIdx.x;
    float v0 = p[t]*SOFT_SCALE, v1 = p[t+256]*SOFT_SCALE;
    red[t] = fmaxf(v0, v1); __syncthreads();
    for(int s = 128; s > 0; s >>= 1){ if(t < s) red[t] = fmaxf(red[t], red[t+s]); __syncthreads(); }
    float mm = red[0]; __syncthreads();
    float e0 = __expf(v0 - mm), e1 = __expf(v1 - mm);
    red[t] = e0 + e1; __syncthreads();
    for(int s = 128; s > 0; s >>= 1){ if(t < s) red[t] += red[t+s]; __syncthreads(); }
    float inv = 1.f/red[0];
    p[t] = e0*inv; p[t+256] = e1*inv;
}

// =============================== host launcher ===============================
extern "C" void kernel_launch(void* const* d_in, const int* in_sizes, int n_in,
                              void* d_out, int out_size){
    const float* x    = (const float*)d_in[0];
    const float* y    = (const float*)d_in[1];
    const float* w5   = (const float*)d_in[2];
    const float* g5   = (const float*)d_in[3];
    const float* b5   = (const float*)d_in[4];
    const float* m5   = (const float*)d_in[5];
    const float* v5   = (const float*)d_in[6];
    const float* w6   = (const float*)d_in[7];
    const float* g6   = (const float*)d_in[8];
    const float* b6   = (const float*)d_in[9];
    const float* m6   = (const float*)d_in[10];
    const float* v6   = (const float*)d_in[11];
    const float* Wq   = (const float*)d_in[12];
    const float* Wk   = (const float*)d_in[13];
    const float* Wv   = (const float*)d_in[14];
    const float* Wout = (const float*)d_in[15];
    const float* bout = (const float*)d_in[16];
    float* out = (float*)d_out;

    float *pxf, *pyf, *pq, *pk, *pv, *psc, *pm, *pAt, *pCt, *pO2;
    __half *pxhi, *pxlo, *pw5ahi, *pw5alo, *pw5dhi, *pw5dlo, *pw6h, *pLth;
    cudaGetSymbolAddress((void**)&pxf, g_xf);
    cudaGetSymbolAddress((void**)&pyf, g_yf);
    cudaGetSymbolAddress((void**)&pq,  g_q);
    cudaGetSymbolAddress((void**)&pk,  g_k);
    cudaGetSymbolAddress((void**)&pv,  g_v);
    cudaGetSymbolAddress((void**)&psc, g_sc);
    cudaGetSymbolAddress((void**)&pm,  g_mg);
    cudaGetSymbolAddress((void**)&pAt, g_At);
    cudaGetSymbolAddress((void**)&pCt, g_Ct);
    cudaGetSymbolAddress((void**)&pO2, g_o2);
    cudaGetSymbolAddress((void**)&pxhi, g_xhi);
    cudaGetSymbolAddress((void**)&pxlo, g_xlo);
    cudaGetSymbolAddress((void**)&pw5ahi, g_w5ahi);
    cudaGetSymbolAddress((void**)&pw5alo, g_w5alo);
    cudaGetSymbolAddress((void**)&pw5dhi, g_w5dhi);
    cudaGetSymbolAddress((void**)&pw5dlo, g_w5dlo);
    cudaGetSymbolAddress((void**)&pw6h, g_w6h);
    cudaGetSymbolAddress((void**)&pLth, g_Lth);

    cudaFuncSetAttribute(gemm_f16t<3>, cudaFuncAttributeMaxDynamicSharedMemorySize, 81920);

    dim3 t2(16, 16);

    k_w6split<<<(C6*N_PTS + 255)/256, 256>>>(w6);
    k_w5split<<<(C5*C_IN + 255)/256, 256>>>(w5, g5, b5, m5, v5);

    for(int br = 0; br < 2; br++){
        const float* p = br ? y : x;
        float* f = br ? pyf : pxf;

        k_xx<<<8, 256>>>(p);
        k_dist<<<528, t2>>>(p);
        k_topk<<<N_PTS, 256>>>();
        k_xsplit<<<dim3(64, 16), 256>>>(p);
        // At/Ct via 3-term fp16 split (full precision path feeding L)
        gemm_f16t<3><<<dim3(16, 4), 256, 81920>>>(pxhi, pxlo, pw5ahi, pw5alo,
                pAt, C_IN/32, C_IN, C_IN, (size_t)C5, N_PTS);
        gemm_f16t<3><<<dim3(16, 4), 256, 81920>>>(pxhi, pxlo, pw5dhi, pw5dlo,
                pCt, C_IN/32, C_IN, C_IN, (size_t)C5, N_PTS);
        k_buildLt<<<dim3(KNN, 64), 256>>>();
        // out2 = w6 @ L   (1-term fp16, 2 CTAs/SM)
        gemm_f16t<1><<<dim3(5, 160), 256, 40960>>>(pw6h, pw6h, pLth, pLth,
                pO2, N_PTS/32, N_PTS, N_PTS, (size_t)NKCOL, C6);
        k_maxpool<<<dim3(2, C6), 256>>>(g6, b6, m6, v6, f);
    }

    // q/k/v
    gemm_nt<<<dim3(8, 8, 1), t2>>>(pxf, Wq, pq, C5, HD, INDIM, INDIM, INDIM, HD, 0, 0, 0, nullptr);
    gemm_nt<<<dim3(8, 8, 1), t2>>>(pyf, Wk, pk, C5, HD, INDIM, INDIM, INDIM, HD, 0, 0, 0, nullptr);
    gemm_nt<<<dim3(8, 8, 1), t2>>>(pyf, Wv, pv, C5, HD, INDIM, INDIM, INDIM, HD, 0, 0, 0, nullptr);

    // scores
    gemm_nt<<<dim3(8, 8, NH), t2>>>(pq, pk, psc, C5, C5, AD, HD, HD, C5,
                                    AD, AD, (long long)C5*C5, nullptr);
    k_softmax<<<NH*C5, 256>>>();

    // weighted
    gemm_nn<<<dim3(1, 8, NH), t2>>>(psc, pv, pm, C5, AD, C5, C5, HD, HD,
                                    (long long)C5*C5, AD, AD);

    // output projection
    gemm_nt<<<dim3((C6+63)/64, 8, 1), t2>>>(pm, Wout, out, C5, C6, HD, HD, HD, C6,
                                            0, 0, 0, bout);
}

// round 17
// speedup vs baseline: 4.5418x; 1.1666x over previous
#include <cuda_runtime.h>
#include <cuda_fp16.h>
#include <math.h>
#include <stdint.h>

#define N_PTS 2048
#define C_IN  512
#define KNN   40
#define C5    512
#define C6    515
#define INDIM C6
#define NKCOL (KNN*C5)         // 20480
#define HD    512
#define NH    8
#define AD    64
#define M_PAD 640
#define SOFT_SCALE 0.04419417382415922f

// ---------------- scratch (device globals, no runtime alloc) ----------------
__device__ float g_dist[(size_t)N_PTS*N_PTS];
__device__ int   g_idx[N_PTS*KNN];
__device__ float g_xx[N_PTS];
__device__ float g_At[(size_t)N_PTS*C5];
__device__ float g_Ct[(size_t)N_PTS*C5];
__device__ float g_tt[C5];
__device__ __half g_xhi[(size_t)N_PTS*C_IN];
__device__ __half g_xlo[(size_t)N_PTS*C_IN];
__device__ __half g_w5ahi[C5*C_IN];
__device__ __half g_w5alo[C5*C_IN];
__device__ __half g_w5dhi[C5*C_IN];
__device__ __half g_w5dlo[C5*C_IN];
__device__ __half g_w6h[(size_t)M_PAD*N_PTS];
__device__ __half g_Lth[(size_t)NKCOL*N_PTS];
__device__ float g_o2[(size_t)C6*NKCOL];
__device__ float g_xf[C5*C6];
__device__ float g_yf[C5*C6];
__device__ float g_q [C5*HD];
__device__ float g_k [C5*HD];
__device__ float g_v [C5*HD];
__device__ float g_sc[(size_t)NH*C5*C5];
__device__ float g_mg[C5*HD];

__device__ __forceinline__ float lrelu(float v){ return v > 0.f ? v : 0.2f*v; }

// ====================== PTX helpers (baseline sm_80+) ======================
__device__ __forceinline__ uint32_t smem_u32(const void* p){
    uint32_t a;
    asm("{ .reg .u64 t; cvta.to.shared.u64 t, %1; cvt.u32.u64 %0, t; }" : "=r"(a) : "l"(p));
    return a;
}
__device__ __forceinline__ void cpa16(uint32_t dst, const void* src){
    asm volatile("cp.async.cg.shared.global [%0], [%1], 16;" :: "r"(dst), "l"(src));
}
#define CPA_COMMIT() asm volatile("cp.async.commit_group;" ::: "memory")
#define CPA_WAIT1()  asm volatile("cp.async.wait_group 1;" ::: "memory")
#define CPA_WAIT0()  asm volatile("cp.async.wait_group 0;" ::: "memory")

#define LDM4(r, ad) \
    asm volatile("ldmatrix.sync.aligned.m8n8.x4.shared.b16 {%0,%1,%2,%3}, [%4];" \
        : "=r"((r)[0]), "=r"((r)[1]), "=r"((r)[2]), "=r"((r)[3]) : "r"(ad))

#define MMA_F16(d, a, b) \
    asm volatile("mma.sync.aligned.m16n8k16.row.col.f32.f16.f16.f32 " \
        "{%0,%1,%2,%3},{%4,%5,%6,%7},{%8,%9},{%0,%1,%2,%3};" \
        : "+f"((d)[0]), "+f"((d)[1]), "+f"((d)[2]), "+f"((d)[3]) \
        : "r"((a)[0]), "r"((a)[1]), "r"((a)[2]), "r"((a)[3]), "r"((b)[0]), "r"((b)[1]))

// ---------------- xx[n] = sum_c x[c,n]^2 ----------------
__global__ void k_xx(const float* __restrict__ x){
    int n = blockIdx.x*blockDim.x + threadIdx.x;
    if(n < N_PTS){
        float s = 0.f;
        for(int c = 0; c < C_IN; c++){ float v = x[(size_t)c*N_PTS + n]; s += v*v; }
        g_xx[n] = s;
    }
}

// ---------------- top-40 per row: radix select + exact jax ordering ----------------
__global__ __launch_bounds__(256) void k_topk(){
    __shared__ int hist[256];
    __shared__ int s_nextb, s_nextneed;
    __shared__ int s_cnt, s_eqcnt;
    __shared__ uint32_t s_selu[KNN];
    __shared__ int      s_seli[KNN];
    __shared__ int      s_eq[64];

    int n = blockIdx.x;
    int t = threadIdx.x;
    const float* row = g_dist + (size_t)n*N_PTS;

    uint32_t u[8];
    #pragma unroll
    for(int i = 0; i < 8; i++){
        uint32_t b = __float_as_uint(row[t + 256*i]);
        u[i] = (b & 0x80000000u) ? ~b : (b | 0x80000000u);
    }

    uint32_t prefix = 0, mask = 0;
    int need = KNN;
    #pragma unroll
    for(int pass = 0; pass < 4; pass++){
        int shift = 24 - pass*8;
        hist[t] = 0;
        __syncthreads();
        #pragma unroll
        for(int i = 0; i < 8; i++)
            if((u[i] & mask) == prefix) atomicAdd(&hist[(u[i] >> shift) & 0xFF], 1);
        __syncthreads();
        int v = hist[t];
        for(int off = 1; off < 256; off <<= 1){
            int w = (t + off < 256) ? hist[t + off] : 0;
            __syncthreads();
            v += w; hist[t] = v;
            __syncthreads();
        }
        int Sn = (t < 255) ? hist[t + 1] : 0;
        if(v >= need && Sn < need){ s_nextb = t; s_nextneed = need - Sn; }
        __syncthreads();
        prefix |= ((uint32_t)s_nextb) << shift;
        mask   |= 0xFFu << shift;
        need = s_nextneed;
        __syncthreads();
    }
    if(t == 0){ s_cnt = 0; s_eqcnt = 0; }
    __syncthreads();
    #pragma unroll
    for(int i = 0; i < 8; i++){
        if(u[i] > prefix){
            int p = atomicAdd(&s_cnt, 1);
            s_selu[p] = u[i]; s_seli[p] = t + 256*i;
        } else if(u[i] == prefix){
            int p = atomicAdd(&s_eqcnt, 1);
            if(p < 64) s_eq[p] = t + 256*i;
        }
    }
    __syncthreads();
    if(t == 0){
        int cnt = s_cnt;
        int e = s_eqcnt < 64 ? s_eqcnt : 64;
        for(int j = 0; j < need; j++){
            int best = 0x7FFFFFFF, bi = -1;
            for(int q = 0; q < e; q++)
                if(s_eq[q] < best){ best = s_eq[q]; bi = q; }
            s_selu[cnt + j] = prefix; s_seli[cnt + j] = best;
            s_eq[bi] = 0x7FFFFFFF;
        }
    }
    __syncthreads();
    if(t < KNN){
        uint32_t mu = s_selu[t]; int mi = s_seli[t];
        int rank = 0;
        #pragma unroll
        for(int q = 0; q < KNN; q++){
            uint32_t qu = s_selu[q]; int qi = s_seli[q];
            rank += (qu > mu) || (qu == mu && qi < mi);
        }
        g_idx[n*KNN + rank] = mi;
    }
}

// ---------------- w5 split (once): fold bn5 scale; fp16 hi/lo; also tt ----------------
__global__ void k_w5split(const float* __restrict__ w5, const float* __restrict__ g5,
                          const float* __restrict__ b5, const float* __restrict__ m5,
                          const float* __restrict__ v5){
    int i = blockIdx.x*256 + threadIdx.x;
    if(i >= C5*C_IN) return;
    int o = i >> 9, c = i & 511;
    float s = g5[o]*rsqrtf(v5[o] + 1e-5f);
    float wa = s*w5[(size_t)o*1024 + c];
    float wd = s*(w5[(size_t)o*1024 + 512 + c] - w5[(size_t)o*1024 + c]);
    __half h;
    h = __float2half(wa); g_w5ahi[i] = h; g_w5alo[i] = __float2half(wa - __half2float(h));
    h = __float2half(wd); g_w5dhi[i] = h; g_w5dlo[i] = __float2half(wd - __half2float(h));
    if(c == 0) g_tt[o] = b5[o] - m5[o]*s;
}

// ---------------- x transpose+split: [c][n] fp32 -> [n][c] fp16 hi/lo ----------------
__global__ __launch_bounds__(256) void k_xsplit(const float* __restrict__ x){
    __shared__ float tile[32][33];
    int n0 = blockIdx.x*32, c0 = blockIdx.y*32;
    int tid = threadIdx.x;
    int a = tid >> 5, b = tid & 31;
    #pragma unroll
    for(int p = 0; p < 4; p++){
        int cl = p*8 + a;
        tile[cl][b] = x[(size_t)(c0+cl)*N_PTS + n0 + b];
    }
    __syncthreads();
    #pragma unroll
    for(int p = 0; p < 4; p++){
        int nl = p*8 + a;
        float v = tile[b][nl];
        __half h = __float2half(v);
        size_t o = (size_t)(n0+nl)*C_IN + c0 + b;
        g_xhi[o] = h;
        g_xlo[o] = __float2half(v - __half2float(h));
    }
}

// ---------------- w6 -> single fp16 ----------------
__global__ void k_w6split(const float* __restrict__ w6){
    int i = blockIdx.x*256 + threadIdx.x;
    if(i < C6*N_PTS) g_w6h[i] = __float2half(w6[i]);
}

// ---------------- build Lt[col][n] single fp16 (transposed) ----------------
__global__ __launch_bounds__(256) void k_buildLt(){
    __shared__ uint32_t sbuf[32][257];
    int k  = blockIdx.x;
    int n0 = blockIdx.y*32;
    int tid = threadIdx.x, wid = tid>>5, lane = tid&31;
    for(int half = 0; half < 2; half++){
        int c0 = half*256;
        #pragma unroll
        for(int q = 0; q < 4; q++){
            int nloc = wid*4 + q;
            int n = n0 + nloc;
            int j = g_idx[n*KNN + k];
            for(int c = lane; c < 256; c += 32){
                float v = g_At[(size_t)j*C5 + c0 + c] + g_Ct[(size_t)n*C5 + c0 + c] + g_tt[c0 + c];
                v = lrelu(v);
                sbuf[nloc][c] = (uint32_t)__half_as_ushort(__float2half(v));
            }
        }
        __syncthreads();
        for(int c = wid; c < 256; c += 8){
            size_t row = (size_t)(k*C5 + c0 + c);
            g_Lth[row*N_PTS + n0 + lane] = __ushort_as_half((unsigned short)(sbuf[lane][c] & 0xFFFFu));
        }
        __syncthreads();
    }
}

// ============ templated warp-MMA fp16 GEMM: C[m][n] = sum_k A[m,k]*B[n,k] ============
// MODE==1: 1-term single fp16; MODE==3: 3-term hi/lo split
// EPI==0: plain store; EPI==1: kNN-dist epilogue (2*acc - xx[m] - xx[n], triangular grid, mirror)
// K-chunk 64, row pitch 144B (128B data + 16B pad -> conflict-free ldmatrix)
#define GM_PITCH 144
#define GM_PLANE (128*GM_PITCH)     // 18432

template<int MODE>
__device__ __forceinline__ void gm_load_chunk(uint32_t sb, int s,
        const __half* Ahi, const __half* Alo,
        const __half* Bhi, const __half* Blo,
        int lda, int ldb, int m0, int n0, int ck, int tid){
    constexpr int ABUF = (MODE == 3) ? 2*GM_PLANE : GM_PLANE;
    constexpr int STG  = 2*ABUF;
    uint32_t base = sb + s*STG;
    #pragma unroll
    for(int p = 0; p < 4; p++){
        int u = p*256 + tid; int row = u >> 3, seg = u & 7;
        cpa16(base + row*GM_PITCH + seg*16, Ahi + (size_t)(m0+row)*lda + ck*64 + seg*8);
    }
    if(MODE == 3){
        #pragma unroll
        for(int p = 0; p < 4; p++){
            int u = p*256 + tid; int row = u >> 3, seg = u & 7;
            cpa16(base + GM_PLANE + row*GM_PITCH + seg*16, Alo + (size_t)(m0+row)*lda + ck*64 + seg*8);
        }
    }
    #pragma unroll
    for(int p = 0; p < 4; p++){
        int u = p*256 + tid; int row = u >> 3, seg = u & 7;
        cpa16(base + ABUF + row*GM_PITCH + seg*16, Bhi + (size_t)(n0+row)*ldb + ck*64 + seg*8);
    }
    if(MODE == 3){
        #pragma unroll
        for(int p = 0; p < 4; p++){
            int u = p*256 + tid; int row = u >> 3, seg = u & 7;
            cpa16(base + ABUF + GM_PLANE + row*GM_PITCH + seg*16, Blo + (size_t)(n0+row)*ldb + ck*64 + seg*8);
        }
    }
}

template<int MODE, int EPI>
__global__ void __launch_bounds__(256, 2) gemm_f16t(
        const __half* __restrict__ Ahi, const __half* __restrict__ Alo,
        const __half* __restrict__ Bhi, const __half* __restrict__ Blo,
        float* __restrict__ C, int nch, int lda, int ldb, size_t ldc, int Mlim){
    constexpr int ABUF = (MODE == 3) ? 2*GM_PLANE : GM_PLANE;
    constexpr int STG  = 2*ABUF;
    extern __shared__ __align__(128) char smem[];
    uint32_t sb = smem_u32(smem);
    int tid = threadIdx.x, lane = tid & 31, wid = tid >> 5;
    int wm = wid & 3, wn = wid >> 2;

    int m0, n0;
    if(EPI == 1){
        int bi = blockIdx.x;
        int by = (int)((sqrtf(8.f*bi + 1.f) - 1.f)*0.5f);
        while(((by + 1)*(by + 2))/2 <= bi) ++by;
        while((by*(by + 1))/2 > bi) --by;
        int bx = bi - (by*(by + 1))/2;
        m0 = by*128; n0 = bx*128;
    } else {
        m0 = blockIdx.x*128; n0 = blockIdx.y*128;
    }

    float acc[2][8][4];
    #pragma unroll
    for(int i = 0; i < 2; i++)
        #pragma unroll
        for(int j = 0; j < 8; j++)
            #pragma unroll
            for(int q = 0; q < 4; q++) acc[i][j][q] = 0.f;

    gm_load_chunk<MODE>(sb, 0, Ahi, Alo, Bhi, Blo, lda, ldb, m0, n0, 0, tid);
    CPA_COMMIT();

    int a_row = wm*32 + (lane & 15);
    int a_col2 = ((lane >> 4) * 8) * 2;
    int b_row = wn*64 + (lane & 7) + ((lane >> 4) << 3);
    int b_col2 = (((lane >> 3) & 1) * 8) * 2;

    for(int c = 0; c < nch; c++){
        if(c + 1 < nch){
            gm_load_chunk<MODE>(sb, (c+1)&1, Ahi, Alo, Bhi, Blo, lda, ldb, m0, n0, c+1, tid);
            CPA_COMMIT();
            CPA_WAIT1();
        } else {
            CPA_WAIT0();
        }
        __syncthreads();

        uint32_t base = sb + (c&1)*STG;
        #pragma unroll
        for(int kb = 0; kb < 4; kb++){
            int kk2 = kb*32;
            uint32_t ah[2][4], al[2][4];
            #pragma unroll
            for(int mt = 0; mt < 2; mt++){
                uint32_t ad = base + (a_row + mt*16)*GM_PITCH + a_col2 + kk2;
                LDM4(ah[mt], ad);
                if(MODE == 3) LDM4(al[mt], ad + GM_PLANE);
            }
            uint32_t bh[8][2], bl[8][2];
            #pragma unroll
            for(int np = 0; np < 4; np++){
                uint32_t bd = base + ABUF + (b_row + np*16)*GM_PITCH + b_col2 + kk2;
                uint32_t r[4];
                LDM4(r, bd);
                bh[np*2][0] = r[0]; bh[np*2][1] = r[1]; bh[np*2+1][0] = r[2]; bh[np*2+1][1] = r[3];
                if(MODE == 3){
                    LDM4(r, bd + GM_PLANE);
                    bl[np*2][0] = r[0]; bl[np*2][1] = r[1]; bl[np*2+1][0] = r[2]; bl[np*2+1][1] = r[3];
                }
            }
            #pragma unroll
            for(int mt = 0; mt < 2; mt++)
                #pragma unroll
                for(int nt = 0; nt < 8; nt++){
                    MMA_F16(acc[mt][nt], ah[mt], bh[nt]);
                    if(MODE == 3){
                        MMA_F16(acc[mt][nt], ah[mt], bl[nt]);
                        MMA_F16(acc[mt][nt], al[mt], bh[nt]);
                    }
                }
        }
        __syncthreads();
    }

    int g = lane >> 2, tg = lane & 3;
    if(EPI == 1){
        #pragma unroll
        for(int mt = 0; mt < 2; mt++){
            #pragma unroll
            for(int rr = 0; rr < 2; rr++){
                int r = wm*32 + mt*16 + g + rr*8;
                float xn = g_xx[m0 + r];
                #pragma unroll
                for(int nt = 0; nt < 8; nt++){
                    int cb = wn*64 + nt*8 + tg*2;
                    float v0 = 2.f*acc[mt][nt][rr*2+0] - xn - g_xx[n0 + cb];
                    float v1 = 2.f*acc[mt][nt][rr*2+1] - xn - g_xx[n0 + cb + 1];
                    *(float2*)(C + (size_t)(m0+r)*ldc + n0 + cb) = make_float2(v0, v1);
                    if(m0 != n0){
                        C[(size_t)(n0+cb)*ldc + m0 + r] = v0;
                        C[(size_t)(n0+cb+1)*ldc + m0 + r] = v1;
                    }
                }
            }
        }
        return;
    }
    #pragma unroll
    for(int mt = 0; mt < 2; mt++){
        int m = m0 + wm*32 + mt*16 + g;
        #pragma unroll
        for(int nt = 0; nt < 8; nt++){
            int col = n0 + wn*64 + nt*8 + tg*2;
            if(m < Mlim)
                *(float2*)(C + (size_t)m*ldc + col) = make_float2(acc[mt][nt][0], acc[mt][nt][1]);
            if(m + 8 < Mlim)
                *(float2*)(C + (size_t)(m+8)*ldc + col) = make_float2(acc[mt][nt][2], acc[mt][nt][3]);
        }
    }
}

// ---------------- generic gemm_nn (attention tail) ----------------
__global__ __launch_bounds__(256) void gemm_nn(const float* __restrict__ A, const float* __restrict__ B,
                       float* __restrict__ C, int M, int N, int K,
                       int lda, int ldb, int ldc,
                       long long sA, long long sB, long long sC){
    A += (size_t)blockIdx.z * sA; B += (size_t)blockIdx.z * sB; C += (size_t)blockIdx.z * sC;
    __shared__ float sAp[64][17];
    __shared__ __align__(16) float sBt[16][64];
    int tx = threadIdx.x, ty = threadIdx.y, t = ty*16 + tx;
    int m0 = blockIdx.y*64, n0 = blockIdx.x*64;
    float acc[4][4] = {};
    for(int k0 = 0; k0 < K; k0 += 16){
        #pragma unroll
        for(int i = 0; i < 4; i++){
            int e = t + i*256; int kt = e & 15; int mi = e >> 4;
            int m = m0 + mi, k = k0 + kt;
            sAp[mi][kt] = (m < M && k < K) ? A[(size_t)m*lda + k] : 0.f;
        }
        #pragma unroll
        for(int i = 0; i < 4; i++){
            int e = t + i*256; int ni = e & 63; int kt = e >> 6;
            int k = k0 + kt, n = n0 + ni;
            sBt[kt][ni] = (k < K && n < N) ? B[(size_t)k*ldb + n] : 0.f;
        }
        __syncthreads();
        #pragma unroll
        for(int kk = 0; kk < 16; kk++){
            float av[4];
            #pragma unroll
            for(int i = 0; i < 4; i++) av[i] = sAp[ty*4+i][kk];
            float4 b4 = *(const float4*)&sBt[kk][tx*4];
            float bv[4] = {b4.x,b4.y,b4.z,b4.w};
            #pragma unroll
            for(int i = 0; i < 4; i++)
                #pragma unroll
                for(int j = 0; j < 4; j++) acc[i][j] += av[i]*bv[j];
        }
        __syncthreads();
    }
    #pragma unroll
    for(int i = 0; i < 4; i++){
        int m = m0 + ty*4 + i; if(m >= M) continue;
        #pragma unroll
        for(int j = 0; j < 4; j++){
            int n = n0 + tx*4 + j; if(n >= N) continue;
            C[(size_t)m*ldc + n] = acc[i][j];
        }
    }
}

// ---------------- generic gemm_nt (+bias) ----------------
__global__ __launch_bounds__(256) void gemm_nt(const float* __restrict__ A, const float* __restrict__ B,
                       float* __restrict__ C, int M, int N, int K,
                       int lda, int ldb, int ldc,
                       long long sA, long long sB, long long sC,
                       const float* __restrict__ bias){
    A += (size_t)blockIdx.z * sA; B += (size_t)blockIdx.z * sB; C += (size_t)blockIdx.z * sC;
    __shared__ float sAp[64][17];
    __shared__ float sBp[64][17];
    int tx = threadIdx.x, ty = threadIdx.y, t = ty*16 + tx;
    int m0 = blockIdx.y*64, n0 = blockIdx.x*64;
    float acc[4][4] = {};
    for(int k0 = 0; k0 < K; k0 += 16){
        #pragma unroll
        for(int i = 0; i < 4; i++){
            int e = t + i*256; int kt = e & 15; int mi = e >> 4;
            int m = m0 + mi, k = k0 + kt;
            sAp[mi][kt] = (m < M && k < K) ? A[(size_t)m*lda + k] : 0.f;
        }
        #pragma unroll
        for(int i = 0; i < 4; i++){
            int e = t + i*256; int kt = e & 15; int ni = e >> 4;
            int n = n0 + ni, k = k0 + kt;
            sBp[ni][kt] = (n < N && k < K) ? B[(size_t)n*ldb + k] : 0.f;
        }
        __syncthreads();
        #pragma unroll
        for(int kk = 0; kk < 16; kk++){
            float av[4], bv[4];
            #pragma unroll
            for(int i = 0; i < 4; i++) av[i] = sAp[ty*4+i][kk];
            #pragma unroll
            for(int j = 0; j < 4; j++) bv[j] = sBp[tx*4+j][kk];
            #pragma unroll
            for(int i = 0; i < 4; i++)
                #pragma unroll
                for(int j = 0; j < 4; j++) acc[i][j] += av[i]*bv[j];
        }
        __syncthreads();
    }
    #pragma unroll
    for(int i = 0; i < 4; i++){
        int m = m0 + ty*4 + i; if(m >= M) continue;
        #pragma unroll
        for(int j = 0; j < 4; j++){
            int n = n0 + tx*4 + j; if(n >= N) continue;
            float bb = bias ? bias[n] : 0.f;
            C[(size_t)m*ldc + n] = acc[i][j] + bb;
        }
    }
}

// ---------------- bn6 + lrelu + max over k ----------------
__global__ void k_maxpool(const float* __restrict__ g6, const float* __restrict__ b6,
                          const float* __restrict__ m6, const float* __restrict__ v6,
                          float* __restrict__ f){
    int o = blockIdx.y;
    int c = blockIdx.x*256 + threadIdx.x;
    float s = g6[o]*rsqrtf(v6[o] + 1e-5f);
    float t = b6[o] - m6[o]*s;
    const float* row = g_o2 + (size_t)o*NKCOL + c;
    float mx = -INFINITY;
    #pragma unroll 8
    for(int k = 0; k < KNN; k++){
        float h = s*row[(size_t)k*C5] + t;
        h = lrelu(h);
        mx = fmaxf(mx, h);
    }
    f[(size_t)c*C6 + o] = mx;
}

// ---------------- row softmax ----------------
__global__ __launch_bounds__(256) void k_softmax(){
    int r = blockIdx.x;
    float* p = g_sc + (size_t)r*C5;
    __shared__ float red[256];
    int t = threadIdx.x;
    float v0 = p[t]*SOFT_SCALE, v1 = p[t+256]*SOFT_SCALE;
    red[t] = fmaxf(v0, v1); __syncthreads();
    for(int s = 128; s > 0; s >>= 1){ if(t < s) red[t] = fmaxf(red[t], red[t+s]); __syncthreads(); }
    float mm = red[0]; __syncthreads();
    float e0 = __expf(v0 - mm), e1 = __expf(v1 - mm);
    red[t] = e0 + e1; __syncthreads();
    for(int s = 128; s > 0; s >>= 1){ if(t < s) red[t] += red[t+s]; __syncthreads(); }
    float inv = 1.f/red[0];
    p[t] = e0*inv; p[t+256] = e1*inv;
}

// =============================== host launcher ===============================
extern "C" void kernel_launch(void* const* d_in, const int* in_sizes, int n_in,
                              void* d_out, int out_size){
    const float* x    = (const float*)d_in[0];
    const float* y    = (const float*)d_in[1];
    const float* w5   = (const float*)d_in[2];
    const float* g5   = (const float*)d_in[3];
    const float* b5   = (const float*)d_in[4];
    const float* m5   = (const float*)d_in[5];
    const float* v5   = (const float*)d_in[6];
    const float* w6   = (const float*)d_in[7];
    const float* g6   = (const float*)d_in[8];
    const float* b6   = (const float*)d_in[9];
    const float* m6   = (const float*)d_in[10];
    const float* v6   = (const float*)d_in[11];
    const float* Wq   = (const float*)d_in[12];
    const float* Wk   = (const float*)d_in[13];
    const float* Wv   = (const float*)d_in[14];
    const float* Wout = (const float*)d_in[15];
    const float* bout = (const float*)d_in[16];
    float* out = (float*)d_out;

    float *pxf, *pyf, *pq, *pk, *pv, *psc, *pm, *pAt, *pCt, *pO2, *pdist;
    __half *pxhi, *pxlo, *pw5ahi, *pw5alo, *pw5dhi, *pw5dlo, *pw6h, *pLth;
    cudaGetSymbolAddress((void**)&pxf, g_xf);
    cudaGetSymbolAddress((void**)&pyf, g_yf);
    cudaGetSymbolAddress((void**)&pq,  g_q);
    cudaGetSymbolAddress((void**)&pk,  g_k);
    cudaGetSymbolAddress((void**)&pv,  g_v);
    cudaGetSymbolAddress((void**)&psc, g_sc);
    cudaGetSymbolAddress((void**)&pm,  g_mg);
    cudaGetSymbolAddress((void**)&pAt, g_At);
    cudaGetSymbolAddress((void**)&pCt, g_Ct);
    cudaGetSymbolAddress((void**)&pO2, g_o2);
    cudaGetSymbolAddress((void**)&pdist, g_dist);
    cudaGetSymbolAddress((void**)&pxhi, g_xhi);
    cudaGetSymbolAddress((void**)&pxlo, g_xlo);
    cudaGetSymbolAddress((void**)&pw5ahi, g_w5ahi);
    cudaGetSymbolAddress((void**)&pw5alo, g_w5alo);
    cudaGetSymbolAddress((void**)&pw5dhi, g_w5dhi);
    cudaGetSymbolAddress((void**)&pw5dlo, g_w5dlo);
    cudaGetSymbolAddress((void**)&pw6h, g_w6h);
    cudaGetSymbolAddress((void**)&pLth, g_Lth);

    const int SM3 = 4*GM_PLANE*2;   // 147456
    const int SM1 = 2*GM_PLANE*2;   // 73728
    cudaFuncSetAttribute(gemm_f16t<3,0>, cudaFuncAttributeMaxDynamicSharedMemorySize, SM3);
    cudaFuncSetAttribute(gemm_f16t<3,1>, cudaFuncAttributeMaxDynamicSharedMemorySize, SM3);
    cudaFuncSetAttribute(gemm_f16t<1,0>, cudaFuncAttributeMaxDynamicSharedMemorySize, SM1);

    dim3 t2(16, 16);

    k_w6split<<<(C6*N_PTS + 255)/256, 256>>>(w6);
    k_w5split<<<(C5*C_IN + 255)/256, 256>>>(w5, g5, b5, m5, v5);

    for(int br = 0; br < 2; br++){
        const float* p = br ? y : x;
        float* f = br ? pyf : pxf;

        k_xx<<<8, 256>>>(p);
        k_xsplit<<<dim3(64, 16), 256>>>(p);
        // dist = 2*(x@x^T) - xx[n] - xx[m], fp16 3-term MMA, triangular grid
        gemm_f16t<3,1><<<136, 256, SM3>>>(pxhi, pxlo, pxhi, pxlo,
                pdist, C_IN/64, C_IN, C_IN, (size_t)N_PTS, N_PTS);
        k_topk<<<N_PTS, 256>>>();
        // At/Ct via 3-term fp16 split
        gemm_f16t<3,0><<<dim3(16, 4), 256, SM3>>>(pxhi, pxlo, pw5ahi, pw5alo,
                pAt, C_IN/64, C_IN, C_IN, (size_t)C5, N_PTS);
        gemm_f16t<3,0><<<dim3(16, 4), 256, SM3>>>(pxhi, pxlo, pw5dhi, pw5dlo,
                pCt, C_IN/64, C_IN, C_IN, (size_t)C5, N_PTS);
        k_buildLt<<<dim3(KNN, 64), 256>>>();
        // out2 = w6 @ L (1-term fp16, 2 CTAs/SM)
        gemm_f16t<1,0><<<dim3(5, 160), 256, SM1>>>(pw6h, pw6h, pLth, pLth,
                pO2, N_PTS/64, N_PTS, N_PTS, (size_t)NKCOL, C6);
        k_maxpool<<<dim3(2, C6), 256>>>(g6, b6, m6, v6, f);
    }

    // q/k/v
    gemm_nt<<<dim3(8, 8, 1), t2>>>(pxf, Wq, pq, C5, HD, INDIM, INDIM, INDIM, HD, 0, 0, 0, nullptr);
    gemm_nt<<<dim3(8, 8, 1), t2>>>(pyf, Wk, pk, C5, HD, INDIM, INDIM, INDIM, HD, 0, 0, 0, nullptr);
    gemm_nt<<<dim3(8, 8, 1), t2>>>(pyf, Wv, pv, C5, HD, INDIM, INDIM, INDIM, HD, 0, 0, 0, nullptr);

    // scores
    gemm_nt<<<dim3(8, 8, NH), t2>>>(pq, pk, psc, C5, C5, AD, HD, HD, C5,
                                    AD, AD, (long long)C5*C5, nullptr);
    k_softmax<<<NH*C5, 256>>>();

    // weighted
    gemm_nn<<<dim3(1, 8, NH), t2>>>(psc, pv, pm, C5, AD, C5, C5, HD, HD,
                                    (long long)C5*C5, AD, AD);

    // output projection
    gemm_nt<<<dim3((C6+63)/64, 8, 1), t2>>>(pm, Wout, out, C5, C6, HD, HD, HD, C6,
                                            0, 0, 0, bout);
}